// round 10
// baseline (speedup 1.0000x reference)
#include <cuda_runtime.h>
#include <math.h>
#include <stdint.h>

#define Bn 8
#define Ln 1024
#define DM 256
#define DI 512
#define NH 16
#define HD 32
#define DS 128
#define CONVD 768
#define DIP 1296
#define Qc 64
#define NC 16   /* Ln/Qc */

// ---------------- scratch (device globals; no mallocs allowed) ----------------
__device__ float g_zx[Bn*Ln*DIP];       // in-proj output
__device__ float g_xs[Bn*Ln*DI];        // conv output, x part (raw, no dt)
__device__ float g_Bmat[Bn*Ln*DS];
__device__ float g_Cmat[Bn*Ln*DS];
__device__ float g_dt[Bn*Ln*NH];
__device__ float g_G[Bn*NC*Qc*Qc];      // TRANSPOSED Gram: Gt[s][t] = C[t]·B[s]
__device__ float g_Acs[Bn*NC*NH*Qc];    // per-chunk inclusive cumsum of dA
__device__ float g_Y[Bn*Ln*DI];         // SSD output accumulator
__device__ float g_st[Bn*NC*NH*HD*DS];  // chunk states -> then prev states
__device__ float g_yf[Bn*Ln*DI];        // gated + rmsnormed
__device__ float g_op[Bn*DM*Ln];        // out-proj, already transposed (b,m,l)
__device__ float g_gn[Bn*8*2];          // groupnorm mean/var

// ---------------- fast math helpers -----------------------------------------
__device__ __forceinline__ float fsilu(float x){
    return __fdividef(x, 1.f + __expf(-x));
}
__device__ __forceinline__ float fmish(float v){
    float t = 1.f + __expf(v);
    return v - v * __fdividef(2.f, t*t + 1.f);
}

// ---------------- tf32 mma helpers -----------------------------------------
__device__ __forceinline__ uint32_t f2tf32(float f){
    uint32_t r; asm("cvt.rna.tf32.f32 %0, %1;" : "=r"(r) : "f"(f)); return r;
}
__device__ __forceinline__ void mma_tf32(float* c, const uint32_t* a, const uint32_t* b){
    asm volatile("mma.sync.aligned.m16n8k8.row.col.f32.tf32.tf32.f32 "
        "{%0,%1,%2,%3}, {%4,%5,%6,%7}, {%8,%9}, {%0,%1,%2,%3};\n"
        : "+f"(c[0]), "+f"(c[1]), "+f"(c[2]), "+f"(c[3])
        : "r"(a[0]), "r"(a[1]), "r"(a[2]), "r"(a[3]),
          "r"(b[0]), "r"(b[1]));
}

// ---------------- K1: in-proj GEMM via tf32 MMA ----------------------------
// zx[m,n] = sum_c x[b,c,l] * W_in[n,c];  m=(b,l): M=8192, N=1296, K=256
__global__ void __launch_bounds__(256) k1_mma(const float* __restrict__ x,
                                              const float* __restrict__ W){
    __shared__ uint32_t As[2][16][132];   // [k][m]
    __shared__ uint32_t Bs[2][16][132];   // [k][n]
    const int n0 = blockIdx.x * 128;
    const int m0 = blockIdx.y * 128;
    const int b  = m0 >> 10;
    const int l0 = m0 & 1023;
    const int tid = threadIdx.x;
    const int wid = tid >> 5, lane = tid & 31;
    const int wm = wid >> 2, wn = wid & 3;      // warp grid 2(m) x 4(n)
    const int lr = lane >> 2, lc = lane & 3;
    float acc[4][4][4] = {};

    const int a_kk = tid >> 5;
    const int a_mm = (tid & 31) << 2;
    const int b_n  = tid & 127;
    const int b_kq = tid >> 7;
    const int n_glob = n0 + b_n;

    #pragma unroll
    for (int i = 0; i < 2; i++){
        int kk = a_kk + i*8;
        float4 v = *reinterpret_cast<const float4*>(&x[((size_t)b*DM + kk)*Ln + l0 + a_mm]);
        uint32_t* p = &As[0][kk][a_mm];
        p[0]=f2tf32(v.x); p[1]=f2tf32(v.y); p[2]=f2tf32(v.z); p[3]=f2tf32(v.w);
    }
    #pragma unroll
    for (int i = 0; i < 2; i++){
        int kq = b_kq + i*2;
        float4 v = make_float4(0.f,0.f,0.f,0.f);
        if (n_glob < DIP) v = *reinterpret_cast<const float4*>(&W[(size_t)n_glob*DM + kq*4]);
        Bs[0][kq*4+0][b_n]=f2tf32(v.x);
        Bs[0][kq*4+1][b_n]=f2tf32(v.y);
        Bs[0][kq*4+2][b_n]=f2tf32(v.z);
        Bs[0][kq*4+3][b_n]=f2tf32(v.w);
    }
    __syncthreads();

    for (int s = 0; s < 16; s++){
        int buf = s & 1;
        float4 av[2], bv[2];
        if (s < 15){
            int c0 = (s+1)*16;
            #pragma unroll
            for (int i = 0; i < 2; i++){
                int kk = a_kk + i*8;
                av[i] = *reinterpret_cast<const float4*>(&x[((size_t)b*DM + c0 + kk)*Ln + l0 + a_mm]);
            }
            #pragma unroll
            for (int i = 0; i < 2; i++){
                int kq = b_kq + i*2;
                bv[i] = (n_glob < DIP)
                    ? *reinterpret_cast<const float4*>(&W[(size_t)n_glob*DM + c0 + kq*4])
                    : make_float4(0.f,0.f,0.f,0.f);
            }
        }
        #pragma unroll
        for (int ksub = 0; ksub < 2; ksub++){
            int ks = ksub*8;
            uint32_t af[4][4], bf[4][2];
            #pragma unroll
            for (int mi = 0; mi < 4; mi++){
                int mr = wm*64 + mi*16 + lr;
                af[mi][0] = As[buf][ks+lc][mr];
                af[mi][1] = As[buf][ks+lc][mr+8];
                af[mi][2] = As[buf][ks+4+lc][mr];
                af[mi][3] = As[buf][ks+4+lc][mr+8];
            }
            #pragma unroll
            for (int ni = 0; ni < 4; ni++){
                int nc = wn*32 + ni*8 + lr;
                bf[ni][0] = Bs[buf][ks+lc][nc];
                bf[ni][1] = Bs[buf][ks+4+lc][nc];
            }
            #pragma unroll
            for (int mi = 0; mi < 4; mi++)
                #pragma unroll
                for (int ni = 0; ni < 4; ni++)
                    mma_tf32(acc[mi][ni], af[mi], bf[ni]);
        }
        if (s < 15){
            #pragma unroll
            for (int i = 0; i < 2; i++){
                int kk = a_kk + i*8;
                uint32_t* p = &As[buf^1][kk][a_mm];
                p[0]=f2tf32(av[i].x); p[1]=f2tf32(av[i].y); p[2]=f2tf32(av[i].z); p[3]=f2tf32(av[i].w);
            }
            #pragma unroll
            for (int i = 0; i < 2; i++){
                int kq = b_kq + i*2;
                Bs[buf^1][kq*4+0][b_n]=f2tf32(bv[i].x);
                Bs[buf^1][kq*4+1][b_n]=f2tf32(bv[i].y);
                Bs[buf^1][kq*4+2][b_n]=f2tf32(bv[i].z);
                Bs[buf^1][kq*4+3][b_n]=f2tf32(bv[i].w);
            }
            __syncthreads();
        }
    }
    #pragma unroll
    for (int mi = 0; mi < 4; mi++){
        int m = m0 + wm*64 + mi*16 + lr;
        #pragma unroll
        for (int ni = 0; ni < 4; ni++){
            int n = n0 + wn*32 + ni*8 + lc*2;
            if (n < DIP){
                g_zx[(size_t)m*DIP + n]       = acc[mi][ni][0];
                g_zx[(size_t)m*DIP + n + 1]   = acc[mi][ni][1];
                g_zx[(size_t)(m+8)*DIP + n]   = acc[mi][ni][2];
                g_zx[(size_t)(m+8)*DIP + n+1] = acc[mi][ni][3];
            }
        }
    }
}

// ---------------- K2: depthwise conv + SiLU + split, and dt=softplus -------
__global__ void k2_conv(const float* __restrict__ conv_w,
                        const float* __restrict__ conv_b,
                        const float* __restrict__ dt_bias){
    int ch = blockIdx.x*256 + threadIdx.x;
    int l0 = blockIdx.y*4, b = blockIdx.z;
    if (ch >= CONVD + NH) return;
    if (ch < CONVD){
        float w0 = conv_w[ch*4+0], w1 = conv_w[ch*4+1];
        float w2 = conv_w[ch*4+2], w3 = conv_w[ch*4+3];
        float bias = conv_b[ch];
        float v[7];
        #pragma unroll
        for (int k = 0; k < 7; k++){
            int ls = l0 - 3 + k;
            v[k] = (ls >= 0) ? g_zx[((size_t)b*Ln + ls)*DIP + DI + ch] : 0.f;
        }
        #pragma unroll
        for (int j = 0; j < 4; j++){
            float acc = bias + w0*v[j] + w1*v[j+1] + w2*v[j+2] + w3*v[j+3];
            float val = fsilu(acc);
            size_t row = (size_t)b*Ln + l0 + j;
            if (ch < DI)            g_xs  [row*DI + ch]            = val;
            else if (ch < DI+DS)    g_Bmat[row*DS + (ch-DI)]       = val;
            else                    g_Cmat[row*DS + (ch-DI-DS)]    = val;
        }
    } else {
        int hh = ch - CONVD;
        float db = dt_bias[hh];
        #pragma unroll
        for (int j = 0; j < 4; j++){
            size_t row = (size_t)b*Ln + l0 + j;
            float v = g_zx[row*DIP + DI + CONVD + hh] + db;
            float sp = (v > 20.f) ? v : log1pf(__expf(v));
            g_dt[row*NH + hh] = sp;
        }
    }
}

// ---------------- S0: Gram Gt[b,c,s,t] = C[t]·B[s] (stored transposed) ------
__global__ void s0_gram(){
    __shared__ float Cs[32][65];
    __shared__ float Bs[32][65];
    int bc = blockIdx.x;            // b*NC + c
    int b = bc / NC, c = bc % NC;
    int l0 = c*Qc;
    int tid = threadIdx.x;
    int tx = tid & 15, ty = tid >> 4;
    float acc[4][4] = {};
    for (int n0 = 0; n0 < DS; n0 += 32){
        #pragma unroll
        for (int k = 0; k < 8; k++){
            int idx = tid + k*256;
            int t = idx >> 5, kk = idx & 31;
            Cs[kk][t] = g_Cmat[((size_t)b*Ln + l0 + t)*DS + n0 + kk];
            Bs[kk][t] = g_Bmat[((size_t)b*Ln + l0 + t)*DS + n0 + kk];
        }
        __syncthreads();
        #pragma unroll
        for (int kk = 0; kk < 32; kk++){
            float a[4], bb[4];
            #pragma unroll
            for (int i = 0; i < 4; i++) a[i]  = Bs[kk][ty*4+i];   // rows = s
            #pragma unroll
            for (int j = 0; j < 4; j++) bb[j] = Cs[kk][tx*4+j];   // cols = t
            #pragma unroll
            for (int i = 0; i < 4; i++)
                #pragma unroll
                for (int j = 0; j < 4; j++) acc[i][j] += a[i]*bb[j];
        }
        __syncthreads();
    }
    #pragma unroll
    for (int i = 0; i < 4; i++)
        #pragma unroll
        for (int j = 0; j < 4; j++)
            g_G[((size_t)bc*Qc + ty*4 + i)*Qc + tx*4 + j] = acc[i][j];
}

// ---------------- S1: per (b,chunk,head): scan, Y_diag(MMA), states(MMA) ----
// B operand streamed from global (L2 reuse across 16 heads) -> small SMEM,
// higher residency (the R8 profile showed latency-bound at occ 29%).
__global__ void __launch_bounds__(256) s1_intra(const float* __restrict__ A_log){
    extern __shared__ float sm[];
    float*    sX   = sm;                         // Qc*36  (X * dt, fp32)
    uint32_t* sWT  = (uint32_t*)(sX + Qc*36);    // Qc*68  (W^T, tf32)
    float*    sAcs = (float*)(sWT + Qc*68);
    float*    sdt  = sAcs + Qc;
    float*    sSe  = sdt + Qc;
    float*    swsum= sSe + Qc;
    int id = blockIdx.x;            // ((b*NC + c)*NH + h)
    int h = id % NH;
    int c = (id / NH) % NC;
    int b = id / (NH*NC);
    int l0 = c*Qc;
    int tid = threadIdx.x;
    int wid = tid >> 5, lane = tid & 31;
    int lr = lane >> 2, lc = lane & 3;

    // warp-shuffle inclusive scan of dA over 64 elements (2 warps)
    float v = 0.f;
    if (tid < Qc){
        float d = g_dt[((size_t)b*Ln + l0 + tid)*NH + h];
        sdt[tid] = d;
        v = d * (-__expf(A_log[h]));
        #pragma unroll
        for (int off = 1; off < 32; off <<= 1){
            float u = __shfl_up_sync(0xffffffffu, v, off);
            if (lane >= off) v += u;
        }
        if (lane == 31) swsum[tid >> 5] = v;
    }
    __syncthreads();
    if (tid < Qc){
        if (tid >= 32) v += swsum[0];
        sAcs[tid] = v;
        g_Acs[(size_t)id*Qc + tid] = v;
    }
    // load X tile scaled by dt
    #pragma unroll
    for (int k = 0; k < 8; k++){
        int idx = tid + k*256;
        int t = idx >> 5, p = idx & 31;
        sX[t*36 + p] = g_xs[(((size_t)b*Ln + l0 + t)*NH + h)*HD + p] * sdt[t];
    }
    __syncthreads();

    if (tid < Qc) sSe[tid] = __expf(sAcs[Qc-1] - sAcs[tid]);
    // build W^T (tf32), zero-filled upper triangle: sWT[s][t]
    const float* Gt = g_G + ((size_t)(b*NC + c)*Qc)*Qc;
    #pragma unroll
    for (int k = 0; k < 16; k++){
        int idx = tid + k*256;
        int s_ = idx >> 6, t_ = idx & 63;
        float w = 0.f;
        if (s_ <= t_) w = Gt[s_*Qc + t_] * __expf(sAcs[t_] - sAcs[s_]);
        sWT[s_*68 + t_] = f2tf32(w);
    }
    __syncthreads();

    if (wid < 4){
        // Y_diag = W @ X : M=64(t), N=32(p), K=64(s); warp wid: rows [16w,16w+16)
        const int m0w = wid*16;
        float acc[4][4] = {};
        const int kmax = 2*(wid+1);   // triangular
        for (int k = 0; k < kmax; k++){
            int ks = k*8;
            uint32_t a[4];
            a[0] = sWT[(ks+lc)*68   + m0w + lr];
            a[1] = sWT[(ks+lc)*68   + m0w + lr + 8];
            a[2] = sWT[(ks+4+lc)*68 + m0w + lr];
            a[3] = sWT[(ks+4+lc)*68 + m0w + lr + 8];
            #pragma unroll
            for (int ni = 0; ni < 4; ni++){
                uint32_t bf[2];
                bf[0] = f2tf32(sX[(ks+lc)*36   + ni*8 + lr]);
                bf[1] = f2tf32(sX[(ks+4+lc)*36 + ni*8 + lr]);
                mma_tf32(acc[ni], a, bf);
            }
        }
        #pragma unroll
        for (int ni = 0; ni < 4; ni++){
            int t = m0w + lr;
            int p = ni*8 + lc*2;
            size_t gi = (((size_t)b*Ln + l0 + t)*NH + h)*HD + p;
            *reinterpret_cast<float2*>(&g_Y[gi]) = make_float2(acc[ni][0], acc[ni][1]);
            size_t gi2 = gi + (size_t)8*NH*HD;
            *reinterpret_cast<float2*>(&g_Y[gi2]) = make_float2(acc[ni][2], acc[ni][3]);
        }
    } else {
        // states S = (X*Se)^T @ B : M=32(p), N=128(n), K=64(t); B from global
        const int ww = wid - 4;
        const int p0 = (ww & 1)*16, n0 = (ww >> 1)*64;
        const float* Bg = g_Bmat + ((size_t)b*Ln + l0)*DS;
        float acc[8][4] = {};
        #pragma unroll
        for (int k = 0; k < 8; k++){
            int ks = k*8;
            int t0 = ks + lc, t1 = ks + 4 + lc;
            float se0 = sSe[t0], se1 = sSe[t1];
            uint32_t a[4];
            a[0] = f2tf32(sX[t0*36 + p0 + lr]     * se0);
            a[1] = f2tf32(sX[t0*36 + p0 + lr + 8] * se0);
            a[2] = f2tf32(sX[t1*36 + p0 + lr]     * se1);
            a[3] = f2tf32(sX[t1*36 + p0 + lr + 8] * se1);
            const float* b0 = Bg + (size_t)t0*DS + n0 + lr;
            const float* b1 = Bg + (size_t)t1*DS + n0 + lr;
            #pragma unroll
            for (int ni = 0; ni < 8; ni++){
                uint32_t bf[2];
                bf[0] = f2tf32(__ldg(b0 + ni*8));
                bf[1] = f2tf32(__ldg(b1 + ni*8));
                mma_tf32(acc[ni], a, bf);
            }
        }
        float* Sp = g_st + (size_t)id*HD*DS;
        #pragma unroll
        for (int ni = 0; ni < 8; ni++){
            int p = p0 + lr;
            int n = n0 + ni*8 + lc*2;
            *reinterpret_cast<float2*>(&Sp[(size_t)p*DS + n])     = make_float2(acc[ni][0], acc[ni][1]);
            *reinterpret_cast<float2*>(&Sp[(size_t)(p+8)*DS + n]) = make_float2(acc[ni][2], acc[ni][3]);
        }
    }
}

// ---------------- S2: sequential inter-chunk recurrence; writes prev -------
__global__ void __launch_bounds__(512) s2_rec(){
    __shared__ float sdec[NC];
    int bh = blockIdx.x;            // b*NH + h
    int b = bh / NH, h = bh % NH;
    if (threadIdx.x < NC){
        int id = (b*NC + threadIdx.x)*NH + h;
        sdec[threadIdx.x] = __expf(g_Acs[(size_t)id*Qc + Qc - 1]);
    }
    __syncthreads();
    const size_t stride = (size_t)NH*HD*DS;
    size_t base = ((size_t)(b*NC)*NH + h)*HD*DS;
    for (int e = threadIdx.x; e < HD*DS; e += 512){
        float st[NC];
        #pragma unroll
        for (int c = 0; c < NC; c++) st[c] = g_st[base + c*stride + e];
        float prev = 0.f;
        #pragma unroll
        for (int c = 0; c < NC; c++){
            g_st[base + c*stride + e] = prev;
            prev = sdec[c]*prev + st[c];
        }
    }
}

// ---------------- S3: Y_off = exp(Acs[t]) * (C @ prev) + D skip (MMA) -------
// C operand streamed from global (L2 reuse across 16 heads) -> small SMEM.
__global__ void __launch_bounds__(128) s3_off(const float* __restrict__ Dp){
    extern __shared__ float sm[];
    float* sP = sm;                 // DS*33  (prev transposed [n][p])
    float* sE = sP + DS*33;         // Qc
    int id = blockIdx.x;
    int h = id % NH;
    int c = (id / NH) % NC;
    int b = id / (NH*NC);
    int l0 = c*Qc;
    int tid = threadIdx.x;
    int wid = tid >> 5, lane = tid & 31;
    int lr = lane >> 2, lc = lane & 3;

    if (tid < Qc) sE[tid] = __expf(g_Acs[(size_t)id*Qc + tid]);
    const float* Sp = g_st + (size_t)id*HD*DS;
    // HD*DS = 4096 elements staged by 128 threads -> exactly 32 iterations.
    #pragma unroll
    for (int k = 0; k < 32; k++){
        int idx = tid + k*128;
        int p = idx >> 7, n = idx & 127;
        sP[n*33 + p] = Sp[idx];
    }
    __syncthreads();

    // Y_off = C @ prev^T : M=64(t), N=32(p), K=128(n); C from global
    const int m0w = wid*16;
    const float* Cg = g_Cmat + ((size_t)b*Ln + l0)*DS;
    float acc[4][4] = {};
    #pragma unroll
    for (int k = 0; k < 16; k++){
        int ks = k*8;
        uint32_t a[4];
        a[0] = f2tf32(__ldg(&Cg[(size_t)(m0w+lr)  *DS + ks + lc]));
        a[1] = f2tf32(__ldg(&Cg[(size_t)(m0w+lr+8)*DS + ks + lc]));
        a[2] = f2tf32(__ldg(&Cg[(size_t)(m0w+lr)  *DS + ks + lc + 4]));
        a[3] = f2tf32(__ldg(&Cg[(size_t)(m0w+lr+8)*DS + ks + lc + 4]));
        #pragma unroll
        for (int ni = 0; ni < 4; ni++){
            uint32_t bf[2];
            bf[0] = f2tf32(sP[(ks+lc)*33   + ni*8 + lr]);
            bf[1] = f2tf32(sP[(ks+4+lc)*33 + ni*8 + lr]);
            mma_tf32(acc[ni], a, bf);
        }
    }
    float dp = Dp[h];
    #pragma unroll
    for (int ni = 0; ni < 4; ni++){
        int t = m0w + lr;
        int p = ni*8 + lc*2;
        float e0 = sE[t], e1 = sE[t+8];
        size_t gi  = (((size_t)b*Ln + l0 + t)*NH + h)*HD + p;
        size_t gi2 = gi + (size_t)8*NH*HD;
        float2 y0 = *reinterpret_cast<float2*>(&g_Y[gi]);
        float2 x0 = *reinterpret_cast<const float2*>(&g_xs[gi]);
        y0.x += e0*acc[ni][0] + dp*x0.x;
        y0.y += e0*acc[ni][1] + dp*x0.y;
        *reinterpret_cast<float2*>(&g_Y[gi]) = y0;
        float2 y1 = *reinterpret_cast<float2*>(&g_Y[gi2]);
        float2 x1 = *reinterpret_cast<const float2*>(&g_xs[gi2]);
        y1.x += e1*acc[ni][2] + dp*x1.x;
        y1.y += e1*acc[ni][3] + dp*x1.y;
        *reinterpret_cast<float2*>(&g_Y[gi2]) = y1;
    }
}

// ---------------- K4: gate with SiLU(z) + RMSNorm over 512 -----------------
__global__ void k4_gate(const float* __restrict__ rms_w){
    __shared__ float red[8];
    __shared__ float s_r;
    int bl = blockIdx.x;
    int tid = threadIdx.x;
    float vloc[2];
    float ss = 0.f;
    #pragma unroll
    for (int i = 0; i < 2; i++){
        int ch = tid + i*256;
        float zv = g_zx[(size_t)bl*DIP + ch];
        float yv = g_Y[(size_t)bl*DI + ch];
        float v = yv * fsilu(zv);
        vloc[i] = v; ss += v*v;
    }
    #pragma unroll
    for (int o = 16; o; o >>= 1) ss += __shfl_xor_sync(~0u, ss, o);
    if ((tid & 31) == 0) red[tid >> 5] = ss;
    __syncthreads();
    if (tid == 0){
        float t = 0.f;
        #pragma unroll
        for (int w = 0; w < 8; w++) t += red[w];
        s_r = rsqrtf(t/512.f + 1e-5f);
    }
    __syncthreads();
    float r = s_r;
    #pragma unroll
    for (int i = 0; i < 2; i++){
        int ch = tid + i*256;
        g_yf[(size_t)bl*DI + ch] = vloc[i]*r*rms_w[ch];
    }
}

// ---------------- K5: out-proj GEMM via tf32 MMA, transposed store ---------
__global__ void __launch_bounds__(256) k5_mma(const float* __restrict__ Wout){
    __shared__ uint32_t As[2][16][132];
    __shared__ uint32_t Bs[2][16][132];
    const int n0 = blockIdx.x * 128;
    const int m0 = blockIdx.y * 128;
    const int tid = threadIdx.x;
    const int wid = tid >> 5, lane = tid & 31;
    const int wm = wid >> 2, wn = wid & 3;
    const int lr = lane >> 2, lc = lane & 3;
    float acc[4][4][4] = {};

    const int t_i  = tid & 127;
    const int t_kq = tid >> 7;

    #pragma unroll
    for (int i = 0; i < 2; i++){
        int kq = t_kq + i*2;
        float4 va = *reinterpret_cast<const float4*>(&g_yf[(size_t)(m0 + t_i)*DI + kq*4]);
        As[0][kq*4+0][t_i]=f2tf32(va.x);
        As[0][kq*4+1][t_i]=f2tf32(va.y);
        As[0][kq*4+2][t_i]=f2tf32(va.z);
        As[0][kq*4+3][t_i]=f2tf32(va.w);
        float4 vb = *reinterpret_cast<const float4*>(&Wout[(size_t)(n0 + t_i)*DI + kq*4]);
        Bs[0][kq*4+0][t_i]=f2tf32(vb.x);
        Bs[0][kq*4+1][t_i]=f2tf32(vb.y);
        Bs[0][kq*4+2][t_i]=f2tf32(vb.z);
        Bs[0][kq*4+3][t_i]=f2tf32(vb.w);
    }
    __syncthreads();

    for (int s = 0; s < 32; s++){
        int buf = s & 1;
        float4 av[2], bv[2];
        if (s < 31){
            int c0 = (s+1)*16;
            #pragma unroll
            for (int i = 0; i < 2; i++){
                int kq = t_kq + i*2;
                av[i] = *reinterpret_cast<const float4*>(&g_yf[(size_t)(m0 + t_i)*DI + c0 + kq*4]);
                bv[i] = *reinterpret_cast<const float4*>(&Wout[(size_t)(n0 + t_i)*DI + c0 + kq*4]);
            }
        }
        #pragma unroll
        for (int ksub = 0; ksub < 2; ksub++){
            int ks = ksub*8;
            uint32_t af[4][4], bf[4][2];
            #pragma unroll
            for (int mi = 0; mi < 4; mi++){
                int mr = wm*64 + mi*16 + lr;
                af[mi][0] = As[buf][ks+lc][mr];
                af[mi][1] = As[buf][ks+lc][mr+8];
                af[mi][2] = As[buf][ks+4+lc][mr];
                af[mi][3] = As[buf][ks+4+lc][mr+8];
            }
            #pragma unroll
            for (int ni = 0; ni < 4; ni++){
                int nc = wn*32 + ni*8 + lr;
                bf[ni][0] = Bs[buf][ks+lc][nc];
                bf[ni][1] = Bs[buf][ks+4+lc][nc];
            }
            #pragma unroll
            for (int mi = 0; mi < 4; mi++)
                #pragma unroll
                for (int ni = 0; ni < 4; ni++)
                    mma_tf32(acc[mi][ni], af[mi], bf[ni]);
        }
        if (s < 31){
            #pragma unroll
            for (int i = 0; i < 2; i++){
                int kq = t_kq + i*2;
                As[buf^1][kq*4+0][t_i]=f2tf32(av[i].x);
                As[buf^1][kq*4+1][t_i]=f2tf32(av[i].y);
                As[buf^1][kq*4+2][t_i]=f2tf32(av[i].z);
                As[buf^1][kq*4+3][t_i]=f2tf32(av[i].w);
                Bs[buf^1][kq*4+0][t_i]=f2tf32(bv[i].x);
                Bs[buf^1][kq*4+1][t_i]=f2tf32(bv[i].y);
                Bs[buf^1][kq*4+2][t_i]=f2tf32(bv[i].z);
                Bs[buf^1][kq*4+3][t_i]=f2tf32(bv[i].w);
            }
            __syncthreads();
        }
    }
    #pragma unroll
    for (int mi = 0; mi < 4; mi++){
        int m = m0 + wm*64 + mi*16 + lr;
        int bb = m >> 10, l = m & 1023;
        #pragma unroll
        for (int ni = 0; ni < 4; ni++){
            int n = n0 + wn*32 + ni*8 + lc*2;
            g_op[((size_t)bb*DM + n  )*Ln + l    ] = acc[mi][ni][0];
            g_op[((size_t)bb*DM + n+1)*Ln + l    ] = acc[mi][ni][1];
            g_op[((size_t)bb*DM + n  )*Ln + l + 8] = acc[mi][ni][2];
            g_op[((size_t)bb*DM + n+1)*Ln + l + 8] = acc[mi][ni][3];
        }
    }
}

// ---------------- K6: GroupNorm statistics ---------------------------------
__global__ void k6_gnstat(){
    __shared__ double rs[8], rs2[8];
    int bg = blockIdx.x;
    int b = bg >> 3, g = bg & 7;
    const float* base = g_op + (size_t)b*DM*Ln + (size_t)g*32*Ln;
    double s = 0, s2 = 0;
    for (int i = threadIdx.x; i < 32*Ln; i += 256){
        double v = base[i]; s += v; s2 += v*v;
    }
    #pragma unroll
    for (int o = 16; o; o >>= 1){
        s  += __shfl_xor_sync(~0u, s,  o);
        s2 += __shfl_xor_sync(~0u, s2, o);
    }
    if ((threadIdx.x & 31) == 0){ rs[threadIdx.x >> 5] = s; rs2[threadIdx.x >> 5] = s2; }
    __syncthreads();
    if (threadIdx.x == 0){
        double S = 0, S2 = 0;
        #pragma unroll
        for (int w = 0; w < 8; w++){ S += rs[w]; S2 += rs2[w]; }
        double mu  = S / (32.0*Ln);
        double var = S2 / (32.0*Ln) - mu*mu;
        g_gn[bg*2]   = (float)mu;
        g_gn[bg*2+1] = (float)var;
    }
}

// ---------------- K7: normalize + affine + Mish ----------------------------
__global__ void k7_mish(const float* __restrict__ gn_w,
                        const float* __restrict__ gn_b,
                        float* __restrict__ out){
    int i = blockIdx.x*256 + threadIdx.x;
    if (i >= Bn*DM*Ln) return;
    int b = i / (DM*Ln);
    int m = (i / Ln) % DM;
    int bg = b*8 + (m >> 5);
    float mu = g_gn[bg*2], var = g_gn[bg*2+1];
    float v = (g_op[i] - mu) * rsqrtf(var + 1e-5f) * gn_w[m] + gn_b[m];
    out[i] = fmish(v);
}

// ---------------------------------------------------------------------------
extern "C" void kernel_launch(void* const* d_in, const int* in_sizes, int n_in,
                              void* d_out, int out_size){
    const float* x       = (const float*)d_in[0];
    const float* W_in    = (const float*)d_in[1];
    const float* conv_w  = (const float*)d_in[2];
    const float* conv_b  = (const float*)d_in[3];
    const float* dt_bias = (const float*)d_in[4];
    const float* A_log   = (const float*)d_in[5];
    const float* Dp      = (const float*)d_in[6];
    const float* rms_w   = (const float*)d_in[7];
    const float* W_out   = (const float*)d_in[8];
    const float* gn_w    = (const float*)d_in[9];
    const float* gn_b    = (const float*)d_in[10];
    float* out = (float*)d_out;

    const int S1_SMEM = (Qc*36 + Qc*68 + Qc*3 + 2) * 4;   // ~27.4 KB
    const int S3_SMEM = (DS*33 + Qc) * 4;                  // ~17.2 KB
    cudaFuncSetAttribute(s1_intra, cudaFuncAttributeMaxDynamicSharedMemorySize, S1_SMEM);
    cudaFuncSetAttribute(s3_off,   cudaFuncAttributeMaxDynamicSharedMemorySize, S3_SMEM);

    k1_mma<<<dim3((DIP + 127)/128, (Bn*Ln)/128), 256>>>(x, W_in);
    k2_conv<<<dim3((CONVD + NH + 255)/256, Ln/4, Bn), 256>>>(conv_w, conv_b, dt_bias);
    s0_gram<<<Bn*NC, 256>>>();
    s1_intra<<<Bn*NC*NH, 256, S1_SMEM>>>(A_log);
    s2_rec<<<Bn*NH, 512>>>();
    s3_off<<<Bn*NC*NH, 128, S3_SMEM>>>(Dp);
    k4_gate<<<Bn*Ln, 256>>>(rms_w);
    k5_mma<<<dim3(DM/128, (Bn*Ln)/128), 256>>>(W_out);
    k6_gnstat<<<Bn*8, 256>>>();
    k7_mish<<<(Bn*DM*Ln + 255)/256, 256>>>(gn_w, gn_b, out);
}

// round 11
// speedup vs baseline: 1.1843x; 1.1843x over previous
#include <cuda_runtime.h>
#include <math.h>
#include <stdint.h>

#define Bn 8
#define Ln 1024
#define DM 256
#define DI 512
#define NH 16
#define HD 32
#define DS 128
#define CONVD 768
#define DIP 1296
#define Qc 64
#define NC 16   /* Ln/Qc */

// ---------------- scratch (device globals; no mallocs allowed) ----------------
__device__ float g_zx[Bn*Ln*DIP];       // in-proj output
__device__ float g_xs[Bn*Ln*DI];        // conv output, x part (raw, no dt)
__device__ float g_Bmat[Bn*Ln*DS];
__device__ float g_Cmat[Bn*Ln*DS];
__device__ float g_dt[Bn*Ln*NH];
__device__ float g_G[Bn*NC*Qc*Qc];      // TRANSPOSED Gram: Gt[s][t] = C[t]·B[s]
__device__ float g_Acs[Bn*NC*NH*Qc];    // per-chunk inclusive cumsum of dA
__device__ float g_Y[Bn*Ln*DI];         // SSD output accumulator
__device__ float g_st[Bn*NC*NH*HD*DS];  // chunk states -> then prev states
__device__ float g_yf[Bn*Ln*DI];        // gated + rmsnormed
__device__ float g_op[Bn*DM*Ln];        // out-proj, already transposed (b,m,l)
__device__ float g_gnpart[Bn*8*8*2];    // per-(b,g,by) partial sum/sumsq from k5
__device__ float g_gn[Bn*8*2];          // groupnorm mean/var

// ---------------- fast math helpers -----------------------------------------
__device__ __forceinline__ float fsilu(float x){
    return __fdividef(x, 1.f + __expf(-x));
}
__device__ __forceinline__ float fmish(float v){
    float t = 1.f + __expf(v);
    return v - v * __fdividef(2.f, t*t + 1.f);
}

// ---------------- tf32 mma helpers -----------------------------------------
__device__ __forceinline__ uint32_t f2tf32(float f){
    uint32_t r; asm("cvt.rna.tf32.f32 %0, %1;" : "=r"(r) : "f"(f)); return r;
}
__device__ __forceinline__ void mma_tf32(float* c, const uint32_t* a, const uint32_t* b){
    asm volatile("mma.sync.aligned.m16n8k8.row.col.f32.tf32.tf32.f32 "
        "{%0,%1,%2,%3}, {%4,%5,%6,%7}, {%8,%9}, {%0,%1,%2,%3};\n"
        : "+f"(c[0]), "+f"(c[1]), "+f"(c[2]), "+f"(c[3])
        : "r"(a[0]), "r"(a[1]), "r"(a[2]), "r"(a[3]),
          "r"(b[0]), "r"(b[1]));
}

// ---------------- K1: in-proj GEMM via tf32 MMA ----------------------------
// zx[m,n] = sum_c x[b,c,l] * W_in[n,c];  m=(b,l): M=8192, N=1296, K=256
__global__ void __launch_bounds__(256) k1_mma(const float* __restrict__ x,
                                              const float* __restrict__ W){
    __shared__ uint32_t As[2][16][132];   // [k][m]
    __shared__ uint32_t Bs[2][16][132];   // [k][n]
    const int n0 = blockIdx.x * 128;
    const int m0 = blockIdx.y * 128;
    const int b  = m0 >> 10;
    const int l0 = m0 & 1023;
    const int tid = threadIdx.x;
    const int wid = tid >> 5, lane = tid & 31;
    const int wm = wid >> 2, wn = wid & 3;      // warp grid 2(m) x 4(n)
    const int lr = lane >> 2, lc = lane & 3;
    float acc[4][4][4] = {};

    const int a_kk = tid >> 5;
    const int a_mm = (tid & 31) << 2;
    const int b_n  = tid & 127;
    const int b_kq = tid >> 7;
    const int n_glob = n0 + b_n;

    #pragma unroll
    for (int i = 0; i < 2; i++){
        int kk = a_kk + i*8;
        float4 v = *reinterpret_cast<const float4*>(&x[((size_t)b*DM + kk)*Ln + l0 + a_mm]);
        uint32_t* p = &As[0][kk][a_mm];
        p[0]=f2tf32(v.x); p[1]=f2tf32(v.y); p[2]=f2tf32(v.z); p[3]=f2tf32(v.w);
    }
    #pragma unroll
    for (int i = 0; i < 2; i++){
        int kq = b_kq + i*2;
        float4 v = make_float4(0.f,0.f,0.f,0.f);
        if (n_glob < DIP) v = *reinterpret_cast<const float4*>(&W[(size_t)n_glob*DM + kq*4]);
        Bs[0][kq*4+0][b_n]=f2tf32(v.x);
        Bs[0][kq*4+1][b_n]=f2tf32(v.y);
        Bs[0][kq*4+2][b_n]=f2tf32(v.z);
        Bs[0][kq*4+3][b_n]=f2tf32(v.w);
    }
    __syncthreads();

    for (int s = 0; s < 16; s++){
        int buf = s & 1;
        float4 av[2], bv[2];
        if (s < 15){
            int c0 = (s+1)*16;
            #pragma unroll
            for (int i = 0; i < 2; i++){
                int kk = a_kk + i*8;
                av[i] = *reinterpret_cast<const float4*>(&x[((size_t)b*DM + c0 + kk)*Ln + l0 + a_mm]);
            }
            #pragma unroll
            for (int i = 0; i < 2; i++){
                int kq = b_kq + i*2;
                bv[i] = (n_glob < DIP)
                    ? *reinterpret_cast<const float4*>(&W[(size_t)n_glob*DM + c0 + kq*4])
                    : make_float4(0.f,0.f,0.f,0.f);
            }
        }
        #pragma unroll
        for (int ksub = 0; ksub < 2; ksub++){
            int ks = ksub*8;
            uint32_t af[4][4], bf[4][2];
            #pragma unroll
            for (int mi = 0; mi < 4; mi++){
                int mr = wm*64 + mi*16 + lr;
                af[mi][0] = As[buf][ks+lc][mr];
                af[mi][1] = As[buf][ks+lc][mr+8];
                af[mi][2] = As[buf][ks+4+lc][mr];
                af[mi][3] = As[buf][ks+4+lc][mr+8];
            }
            #pragma unroll
            for (int ni = 0; ni < 4; ni++){
                int nc = wn*32 + ni*8 + lr;
                bf[ni][0] = Bs[buf][ks+lc][nc];
                bf[ni][1] = Bs[buf][ks+4+lc][nc];
            }
            #pragma unroll
            for (int mi = 0; mi < 4; mi++)
                #pragma unroll
                for (int ni = 0; ni < 4; ni++)
                    mma_tf32(acc[mi][ni], af[mi], bf[ni]);
        }
        if (s < 15){
            #pragma unroll
            for (int i = 0; i < 2; i++){
                int kk = a_kk + i*8;
                uint32_t* p = &As[buf^1][kk][a_mm];
                p[0]=f2tf32(av[i].x); p[1]=f2tf32(av[i].y); p[2]=f2tf32(av[i].z); p[3]=f2tf32(av[i].w);
            }
            #pragma unroll
            for (int i = 0; i < 2; i++){
                int kq = b_kq + i*2;
                Bs[buf^1][kq*4+0][b_n]=f2tf32(bv[i].x);
                Bs[buf^1][kq*4+1][b_n]=f2tf32(bv[i].y);
                Bs[buf^1][kq*4+2][b_n]=f2tf32(bv[i].z);
                Bs[buf^1][kq*4+3][b_n]=f2tf32(bv[i].w);
            }
            __syncthreads();
        }
    }
    #pragma unroll
    for (int mi = 0; mi < 4; mi++){
        int m = m0 + wm*64 + mi*16 + lr;
        #pragma unroll
        for (int ni = 0; ni < 4; ni++){
            int n = n0 + wn*32 + ni*8 + lc*2;
            if (n < DIP){
                g_zx[(size_t)m*DIP + n]       = acc[mi][ni][0];
                g_zx[(size_t)m*DIP + n + 1]   = acc[mi][ni][1];
                g_zx[(size_t)(m+8)*DIP + n]   = acc[mi][ni][2];
                g_zx[(size_t)(m+8)*DIP + n+1] = acc[mi][ni][3];
            }
        }
    }
}

// ---------------- K2: depthwise conv + SiLU + split, and dt=softplus -------
__global__ void k2_conv(const float* __restrict__ conv_w,
                        const float* __restrict__ conv_b,
                        const float* __restrict__ dt_bias){
    int ch = blockIdx.x*256 + threadIdx.x;
    int l0 = blockIdx.y*4, b = blockIdx.z;
    if (ch >= CONVD + NH) return;
    if (ch < CONVD){
        float w0 = conv_w[ch*4+0], w1 = conv_w[ch*4+1];
        float w2 = conv_w[ch*4+2], w3 = conv_w[ch*4+3];
        float bias = conv_b[ch];
        float v[7];
        #pragma unroll
        for (int k = 0; k < 7; k++){
            int ls = l0 - 3 + k;
            v[k] = (ls >= 0) ? g_zx[((size_t)b*Ln + ls)*DIP + DI + ch] : 0.f;
        }
        #pragma unroll
        for (int j = 0; j < 4; j++){
            float acc = bias + w0*v[j] + w1*v[j+1] + w2*v[j+2] + w3*v[j+3];
            float val = fsilu(acc);
            size_t row = (size_t)b*Ln + l0 + j;
            if (ch < DI)            g_xs  [row*DI + ch]            = val;
            else if (ch < DI+DS)    g_Bmat[row*DS + (ch-DI)]       = val;
            else                    g_Cmat[row*DS + (ch-DI-DS)]    = val;
        }
    } else {
        int hh = ch - CONVD;
        float db = dt_bias[hh];
        #pragma unroll
        for (int j = 0; j < 4; j++){
            size_t row = (size_t)b*Ln + l0 + j;
            float v = g_zx[row*DIP + DI + CONVD + hh] + db;
            float sp = (v > 20.f) ? v : log1pf(__expf(v));
            g_dt[row*NH + hh] = sp;
        }
    }
}

// ---------------- S0: Gram Gt[b,c,s,t] = C[t]·B[s] (stored transposed) ------
__global__ void s0_gram(){
    __shared__ float Cs[32][65];
    __shared__ float Bs[32][65];
    int bc = blockIdx.x;            // b*NC + c
    int b = bc / NC, c = bc % NC;
    int l0 = c*Qc;
    int tid = threadIdx.x;
    int tx = tid & 15, ty = tid >> 4;
    float acc[4][4] = {};
    for (int n0 = 0; n0 < DS; n0 += 32){
        #pragma unroll
        for (int k = 0; k < 8; k++){
            int idx = tid + k*256;
            int t = idx >> 5, kk = idx & 31;
            Cs[kk][t] = g_Cmat[((size_t)b*Ln + l0 + t)*DS + n0 + kk];
            Bs[kk][t] = g_Bmat[((size_t)b*Ln + l0 + t)*DS + n0 + kk];
        }
        __syncthreads();
        #pragma unroll
        for (int kk = 0; kk < 32; kk++){
            float a[4], bb[4];
            #pragma unroll
            for (int i = 0; i < 4; i++) a[i]  = Bs[kk][ty*4+i];   // rows = s
            #pragma unroll
            for (int j = 0; j < 4; j++) bb[j] = Cs[kk][tx*4+j];   // cols = t
            #pragma unroll
            for (int i = 0; i < 4; i++)
                #pragma unroll
                for (int j = 0; j < 4; j++) acc[i][j] += a[i]*bb[j];
        }
        __syncthreads();
    }
    #pragma unroll
    for (int i = 0; i < 4; i++)
        #pragma unroll
        for (int j = 0; j < 4; j++)
            g_G[((size_t)bc*Qc + ty*4 + i)*Qc + tx*4 + j] = acc[i][j];
}

// ---------------- S1: per (b,chunk,head): scan, Y_diag(MMA), states(MMA) ----
// R8 version: all MMA operands staged in SMEM (R9 showed LDG operands in the
// dependent inner loop lengthen the critical chain and regress).
__global__ void __launch_bounds__(256) s1_intra(const float* __restrict__ A_log){
    extern __shared__ float sm[];
    float*    sX   = sm;                         // Qc*36  (X * dt, fp32)
    float*    sB   = sX + Qc*36;                 // Qc*132 (B tile, fp32)
    uint32_t* sWT  = (uint32_t*)(sB + Qc*132);   // Qc*68  (W^T, tf32)
    float*    sAcs = (float*)(sWT + Qc*68);
    float*    sdt  = sAcs + Qc;
    float*    sSe  = sdt + Qc;
    float*    swsum= sSe + Qc;
    int id = blockIdx.x;            // ((b*NC + c)*NH + h)
    int h = id % NH;
    int c = (id / NH) % NC;
    int b = id / (NH*NC);
    int l0 = c*Qc;
    int tid = threadIdx.x;
    int wid = tid >> 5, lane = tid & 31;
    int lr = lane >> 2, lc = lane & 3;

    // warp-shuffle inclusive scan of dA over 64 elements (2 warps)
    float v = 0.f;
    if (tid < Qc){
        float d = g_dt[((size_t)b*Ln + l0 + tid)*NH + h];
        sdt[tid] = d;
        v = d * (-__expf(A_log[h]));
        #pragma unroll
        for (int off = 1; off < 32; off <<= 1){
            float u = __shfl_up_sync(0xffffffffu, v, off);
            if (lane >= off) v += u;
        }
        if (lane == 31) swsum[tid >> 5] = v;
    }
    __syncthreads();
    if (tid < Qc){
        if (tid >= 32) v += swsum[0];
        sAcs[tid] = v;
        g_Acs[(size_t)id*Qc + tid] = v;
    }
    // load X tile scaled by dt
    #pragma unroll
    for (int k = 0; k < 8; k++){
        int idx = tid + k*256;
        int t = idx >> 5, p = idx & 31;
        sX[t*36 + p] = g_xs[(((size_t)b*Ln + l0 + t)*NH + h)*HD + p] * sdt[t];
    }
    // stage B tile (fp32) [t][n], pad 132
    #pragma unroll
    for (int k = 0; k < 8; k++){
        int idx = tid + k*256;
        int t = idx >> 5, c4 = (idx & 31)*4;
        float4 bv = *reinterpret_cast<const float4*>(&g_Bmat[((size_t)b*Ln + l0 + t)*DS + c4]);
        *reinterpret_cast<float4*>(&sB[t*132 + c4]) = bv;
    }
    __syncthreads();

    if (tid < Qc) sSe[tid] = __expf(sAcs[Qc-1] - sAcs[tid]);
    // build W^T (tf32), zero-filled upper triangle: sWT[s][t]
    const float* Gt = g_G + ((size_t)(b*NC + c)*Qc)*Qc;
    #pragma unroll
    for (int k = 0; k < 16; k++){
        int idx = tid + k*256;
        int s_ = idx >> 6, t_ = idx & 63;
        float w = 0.f;
        if (s_ <= t_) w = Gt[s_*Qc + t_] * __expf(sAcs[t_] - sAcs[s_]);
        sWT[s_*68 + t_] = f2tf32(w);
    }
    __syncthreads();

    if (wid < 4){
        // Y_diag = W @ X : M=64(t), N=32(p), K=64(s); warp wid: rows [16w,16w+16)
        const int m0w = wid*16;
        float acc[4][4] = {};
        const int kmax = 2*(wid+1);   // triangular
        for (int k = 0; k < kmax; k++){
            int ks = k*8;
            uint32_t a[4];
            a[0] = sWT[(ks+lc)*68   + m0w + lr];
            a[1] = sWT[(ks+lc)*68   + m0w + lr + 8];
            a[2] = sWT[(ks+4+lc)*68 + m0w + lr];
            a[3] = sWT[(ks+4+lc)*68 + m0w + lr + 8];
            #pragma unroll
            for (int ni = 0; ni < 4; ni++){
                uint32_t bf[2];
                bf[0] = f2tf32(sX[(ks+lc)*36   + ni*8 + lr]);
                bf[1] = f2tf32(sX[(ks+4+lc)*36 + ni*8 + lr]);
                mma_tf32(acc[ni], a, bf);
            }
        }
        #pragma unroll
        for (int ni = 0; ni < 4; ni++){
            int t = m0w + lr;
            int p = ni*8 + lc*2;
            size_t gi = (((size_t)b*Ln + l0 + t)*NH + h)*HD + p;
            *reinterpret_cast<float2*>(&g_Y[gi]) = make_float2(acc[ni][0], acc[ni][1]);
            size_t gi2 = gi + (size_t)8*NH*HD;
            *reinterpret_cast<float2*>(&g_Y[gi2]) = make_float2(acc[ni][2], acc[ni][3]);
        }
    } else {
        // states S = (X*Se)^T @ B : M=32(p), N=128(n), K=64(t)
        const int ww = wid - 4;
        const int p0 = (ww & 1)*16, n0 = (ww >> 1)*64;
        float acc[8][4] = {};
        #pragma unroll
        for (int k = 0; k < 8; k++){
            int ks = k*8;
            int t0 = ks + lc, t1 = ks + 4 + lc;
            float se0 = sSe[t0], se1 = sSe[t1];
            uint32_t a[4];
            a[0] = f2tf32(sX[t0*36 + p0 + lr]     * se0);
            a[1] = f2tf32(sX[t0*36 + p0 + lr + 8] * se0);
            a[2] = f2tf32(sX[t1*36 + p0 + lr]     * se1);
            a[3] = f2tf32(sX[t1*36 + p0 + lr + 8] * se1);
            #pragma unroll
            for (int ni = 0; ni < 8; ni++){
                uint32_t bf[2];
                bf[0] = f2tf32(sB[t0*132 + n0 + ni*8 + lr]);
                bf[1] = f2tf32(sB[t1*132 + n0 + ni*8 + lr]);
                mma_tf32(acc[ni], a, bf);
            }
        }
        float* Sp = g_st + (size_t)id*HD*DS;
        #pragma unroll
        for (int ni = 0; ni < 8; ni++){
            int p = p0 + lr;
            int n = n0 + ni*8 + lc*2;
            *reinterpret_cast<float2*>(&Sp[(size_t)p*DS + n])     = make_float2(acc[ni][0], acc[ni][1]);
            *reinterpret_cast<float2*>(&Sp[(size_t)(p+8)*DS + n]) = make_float2(acc[ni][2], acc[ni][3]);
        }
    }
}

// ---------------- S2: sequential inter-chunk recurrence; writes prev -------
__global__ void __launch_bounds__(512) s2_rec(){
    __shared__ float sdec[NC];
    int bh = blockIdx.x;            // b*NH + h
    int b = bh / NH, h = bh % NH;
    if (threadIdx.x < NC){
        int id = (b*NC + threadIdx.x)*NH + h;
        sdec[threadIdx.x] = __expf(g_Acs[(size_t)id*Qc + Qc - 1]);
    }
    __syncthreads();
    const size_t stride = (size_t)NH*HD*DS;
    size_t base = ((size_t)(b*NC)*NH + h)*HD*DS;
    for (int e = threadIdx.x; e < HD*DS; e += 512){
        float st[NC];
        #pragma unroll
        for (int c = 0; c < NC; c++) st[c] = g_st[base + c*stride + e];
        float prev = 0.f;
        #pragma unroll
        for (int c = 0; c < NC; c++){
            g_st[base + c*stride + e] = prev;
            prev = sdec[c]*prev + st[c];
        }
    }
}

// ---------------- S3: Y_off = exp(Acs[t]) * (C @ prev) + D skip (MMA) -------
// R8 version: C staged in SMEM.
__global__ void __launch_bounds__(128) s3_off(const float* __restrict__ Dp){
    extern __shared__ float sm[];
    float* sC = sm;                 // Qc*132 (C tile fp32 [t][n])
    float* sP = sC + Qc*132;        // DS*33  (prev transposed [n][p])
    float* sE = sP + DS*33;         // Qc
    int id = blockIdx.x;
    int h = id % NH;
    int c = (id / NH) % NC;
    int b = id / (NH*NC);
    int l0 = c*Qc;
    int tid = threadIdx.x;
    int wid = tid >> 5, lane = tid & 31;
    int lr = lane >> 2, lc = lane & 3;

    if (tid < Qc) sE[tid] = __expf(g_Acs[(size_t)id*Qc + tid]);
    #pragma unroll
    for (int k = 0; k < 16; k++){
        int idx = tid + k*128;
        int t = idx >> 5, c4 = (idx & 31)*4;
        float4 cv = *reinterpret_cast<const float4*>(&g_Cmat[((size_t)b*Ln + l0 + t)*DS + c4]);
        *reinterpret_cast<float4*>(&sC[t*132 + c4]) = cv;
    }
    const float* Sp = g_st + (size_t)id*HD*DS;
    // HD*DS = 4096 elements staged by 128 threads -> exactly 32 iterations.
    #pragma unroll
    for (int k = 0; k < 32; k++){
        int idx = tid + k*128;
        int p = idx >> 7, n = idx & 127;
        sP[n*33 + p] = Sp[idx];
    }
    __syncthreads();

    // Y_off = C @ prev^T : M=64(t), N=32(p), K=128(n)
    const int m0w = wid*16;
    float acc[4][4] = {};
    #pragma unroll
    for (int k = 0; k < 16; k++){
        int ks = k*8;
        uint32_t a[4];
        a[0] = f2tf32(sC[(m0w+lr)*132   + ks + lc]);
        a[1] = f2tf32(sC[(m0w+lr+8)*132 + ks + lc]);
        a[2] = f2tf32(sC[(m0w+lr)*132   + ks + lc + 4]);
        a[3] = f2tf32(sC[(m0w+lr+8)*132 + ks + lc + 4]);
        #pragma unroll
        for (int ni = 0; ni < 4; ni++){
            uint32_t bf[2];
            bf[0] = f2tf32(sP[(ks+lc)*33   + ni*8 + lr]);
            bf[1] = f2tf32(sP[(ks+4+lc)*33 + ni*8 + lr]);
            mma_tf32(acc[ni], a, bf);
        }
    }
    float dp = Dp[h];
    #pragma unroll
    for (int ni = 0; ni < 4; ni++){
        int t = m0w + lr;
        int p = ni*8 + lc*2;
        float e0 = sE[t], e1 = sE[t+8];
        size_t gi  = (((size_t)b*Ln + l0 + t)*NH + h)*HD + p;
        size_t gi2 = gi + (size_t)8*NH*HD;
        float2 y0 = *reinterpret_cast<float2*>(&g_Y[gi]);
        float2 x0 = *reinterpret_cast<const float2*>(&g_xs[gi]);
        y0.x += e0*acc[ni][0] + dp*x0.x;
        y0.y += e0*acc[ni][1] + dp*x0.y;
        *reinterpret_cast<float2*>(&g_Y[gi]) = y0;
        float2 y1 = *reinterpret_cast<float2*>(&g_Y[gi2]);
        float2 x1 = *reinterpret_cast<const float2*>(&g_xs[gi2]);
        y1.x += e1*acc[ni][2] + dp*x1.x;
        y1.y += e1*acc[ni][3] + dp*x1.y;
        *reinterpret_cast<float2*>(&g_Y[gi2]) = y1;
    }
}

// ---------------- K4: gate with SiLU(z) + RMSNorm over 512 -----------------
__global__ void k4_gate(const float* __restrict__ rms_w){
    __shared__ float red[8];
    __shared__ float s_r;
    int bl = blockIdx.x;
    int tid = threadIdx.x;
    float vloc[2];
    float ss = 0.f;
    #pragma unroll
    for (int i = 0; i < 2; i++){
        int ch = tid + i*256;
        float zv = g_zx[(size_t)bl*DIP + ch];
        float yv = g_Y[(size_t)bl*DI + ch];
        float v = yv * fsilu(zv);
        vloc[i] = v; ss += v*v;
    }
    #pragma unroll
    for (int o = 16; o; o >>= 1) ss += __shfl_xor_sync(~0u, ss, o);
    if ((tid & 31) == 0) red[tid >> 5] = ss;
    __syncthreads();
    if (tid == 0){
        float t = 0.f;
        #pragma unroll
        for (int w = 0; w < 8; w++) t += red[w];
        s_r = rsqrtf(t/512.f + 1e-5f);
    }
    __syncthreads();
    float r = s_r;
    #pragma unroll
    for (int i = 0; i < 2; i++){
        int ch = tid + i*256;
        g_yf[(size_t)bl*DI + ch] = vloc[i]*r*rms_w[ch];
    }
}

// ---------------- K5: out-proj GEMM via tf32 MMA, transposed store ---------
// Epilogue also emits GroupNorm partial sums: each warp's output tile lies
// entirely in one group (n = wn*32 + ni*8 + lc*2 spans [wn*32, wn*32+32)),
// so a warp shfl-reduction gives deterministic per-(block,group) partials.
__global__ void __launch_bounds__(256) k5_mma(const float* __restrict__ Wout){
    __shared__ uint32_t As[2][16][132];
    __shared__ uint32_t Bs[2][16][132];
    __shared__ float s_part[8][2];
    const int n0 = blockIdx.x * 128;
    const int m0 = blockIdx.y * 128;
    const int tid = threadIdx.x;
    const int wid = tid >> 5, lane = tid & 31;
    const int wm = wid >> 2, wn = wid & 3;
    const int lr = lane >> 2, lc = lane & 3;
    float acc[4][4][4] = {};

    const int t_i  = tid & 127;
    const int t_kq = tid >> 7;

    #pragma unroll
    for (int i = 0; i < 2; i++){
        int kq = t_kq + i*2;
        float4 va = *reinterpret_cast<const float4*>(&g_yf[(size_t)(m0 + t_i)*DI + kq*4]);
        As[0][kq*4+0][t_i]=f2tf32(va.x);
        As[0][kq*4+1][t_i]=f2tf32(va.y);
        As[0][kq*4+2][t_i]=f2tf32(va.z);
        As[0][kq*4+3][t_i]=f2tf32(va.w);
        float4 vb = *reinterpret_cast<const float4*>(&Wout[(size_t)(n0 + t_i)*DI + kq*4]);
        Bs[0][kq*4+0][t_i]=f2tf32(vb.x);
        Bs[0][kq*4+1][t_i]=f2tf32(vb.y);
        Bs[0][kq*4+2][t_i]=f2tf32(vb.z);
        Bs[0][kq*4+3][t_i]=f2tf32(vb.w);
    }
    __syncthreads();

    for (int s = 0; s < 32; s++){
        int buf = s & 1;
        float4 av[2], bv[2];
        if (s < 31){
            int c0 = (s+1)*16;
            #pragma unroll
            for (int i = 0; i < 2; i++){
                int kq = t_kq + i*2;
                av[i] = *reinterpret_cast<const float4*>(&g_yf[(size_t)(m0 + t_i)*DI + c0 + kq*4]);
                bv[i] = *reinterpret_cast<const float4*>(&Wout[(size_t)(n0 + t_i)*DI + c0 + kq*4]);
            }
        }
        #pragma unroll
        for (int ksub = 0; ksub < 2; ksub++){
            int ks = ksub*8;
            uint32_t af[4][4], bf[4][2];
            #pragma unroll
            for (int mi = 0; mi < 4; mi++){
                int mr = wm*64 + mi*16 + lr;
                af[mi][0] = As[buf][ks+lc][mr];
                af[mi][1] = As[buf][ks+lc][mr+8];
                af[mi][2] = As[buf][ks+4+lc][mr];
                af[mi][3] = As[buf][ks+4+lc][mr+8];
            }
            #pragma unroll
            for (int ni = 0; ni < 4; ni++){
                int nc = wn*32 + ni*8 + lr;
                bf[ni][0] = Bs[buf][ks+lc][nc];
                bf[ni][1] = Bs[buf][ks+4+lc][nc];
            }
            #pragma unroll
            for (int mi = 0; mi < 4; mi++)
                #pragma unroll
                for (int ni = 0; ni < 4; ni++)
                    mma_tf32(acc[mi][ni], af[mi], bf[ni]);
        }
        if (s < 31){
            #pragma unroll
            for (int i = 0; i < 2; i++){
                int kq = t_kq + i*2;
                As[buf^1][kq*4+0][t_i]=f2tf32(av[i].x);
                As[buf^1][kq*4+1][t_i]=f2tf32(av[i].y);
                As[buf^1][kq*4+2][t_i]=f2tf32(av[i].z);
                As[buf^1][kq*4+3][t_i]=f2tf32(av[i].w);
                Bs[buf^1][kq*4+0][t_i]=f2tf32(bv[i].x);
                Bs[buf^1][kq*4+1][t_i]=f2tf32(bv[i].y);
                Bs[buf^1][kq*4+2][t_i]=f2tf32(bv[i].z);
                Bs[buf^1][kq*4+3][t_i]=f2tf32(bv[i].w);
            }
            __syncthreads();
        }
    }
    // store transposed + accumulate GroupNorm partials
    float psum = 0.f, psq = 0.f;
    #pragma unroll
    for (int mi = 0; mi < 4; mi++){
        int m = m0 + wm*64 + mi*16 + lr;
        int bb = m >> 10, l = m & 1023;
        #pragma unroll
        for (int ni = 0; ni < 4; ni++){
            int n = n0 + wn*32 + ni*8 + lc*2;
            g_op[((size_t)bb*DM + n  )*Ln + l    ] = acc[mi][ni][0];
            g_op[((size_t)bb*DM + n+1)*Ln + l    ] = acc[mi][ni][1];
            g_op[((size_t)bb*DM + n  )*Ln + l + 8] = acc[mi][ni][2];
            g_op[((size_t)bb*DM + n+1)*Ln + l + 8] = acc[mi][ni][3];
            #pragma unroll
            for (int q = 0; q < 4; q++){
                float vv = acc[mi][ni][q];
                psum += vv; psq += vv*vv;
            }
        }
    }
    #pragma unroll
    for (int o = 16; o; o >>= 1){
        psum += __shfl_xor_sync(~0u, psum, o);
        psq  += __shfl_xor_sync(~0u, psq,  o);
    }
    if (lane == 0){ s_part[wid][0] = psum; s_part[wid][1] = psq; }
    __syncthreads();
    if (tid < 4){
        int g = blockIdx.x*4 + tid;          // global group 0..7
        int b = blockIdx.y >> 3, by = blockIdx.y & 7;
        float S  = s_part[tid][0] + s_part[tid+4][0];
        float S2 = s_part[tid][1] + s_part[tid+4][1];
        int slot = ((b*8 + g)*8 + by)*2;
        g_gnpart[slot]   = S;
        g_gnpart[slot+1] = S2;
    }
}

// ---------------- K6b: finalize GroupNorm stats from k5 partials -----------
__global__ void k6b_gnfin(){
    int i = threadIdx.x;            // 0..63 = b*8 + g
    if (i >= Bn*8) return;
    double S = 0.0, S2 = 0.0;
    #pragma unroll
    for (int by = 0; by < 8; by++){
        S  += (double)g_gnpart[((i)*8 + by)*2];
        S2 += (double)g_gnpart[((i)*8 + by)*2 + 1];
    }
    double N = 32.0*Ln;
    double mu  = S / N;
    double var = S2 / N - mu*mu;
    g_gn[i*2]   = (float)mu;
    g_gn[i*2+1] = (float)var;
}

// ---------------- K7: normalize + affine + Mish ----------------------------
__global__ void k7_mish(const float* __restrict__ gn_w,
                        const float* __restrict__ gn_b,
                        float* __restrict__ out){
    int i = blockIdx.x*256 + threadIdx.x;
    if (i >= Bn*DM*Ln) return;
    int b = i / (DM*Ln);
    int m = (i / Ln) % DM;
    int bg = b*8 + (m >> 5);
    float mu = g_gn[bg*2], var = g_gn[bg*2+1];
    float v = (g_op[i] - mu) * rsqrtf(var + 1e-5f) * gn_w[m] + gn_b[m];
    out[i] = fmish(v);
}

// ---------------------------------------------------------------------------
extern "C" void kernel_launch(void* const* d_in, const int* in_sizes, int n_in,
                              void* d_out, int out_size){
    const float* x       = (const float*)d_in[0];
    const float* W_in    = (const float*)d_in[1];
    const float* conv_w  = (const float*)d_in[2];
    const float* conv_b  = (const float*)d_in[3];
    const float* dt_bias = (const float*)d_in[4];
    const float* A_log   = (const float*)d_in[5];
    const float* Dp      = (const float*)d_in[6];
    const float* rms_w   = (const float*)d_in[7];
    const float* W_out   = (const float*)d_in[8];
    const float* gn_w    = (const float*)d_in[9];
    const float* gn_b    = (const float*)d_in[10];
    float* out = (float*)d_out;

    const int S1_SMEM = (Qc*36 + Qc*132 + Qc*68 + Qc*3 + 2) * 4;   // ~61.2 KB
    const int S3_SMEM = (Qc*132 + DS*33 + Qc) * 4;                  // ~50.9 KB
    cudaFuncSetAttribute(s1_intra, cudaFuncAttributeMaxDynamicSharedMemorySize, S1_SMEM);
    cudaFuncSetAttribute(s3_off,   cudaFuncAttributeMaxDynamicSharedMemorySize, S3_SMEM);

    k1_mma<<<dim3((DIP + 127)/128, (Bn*Ln)/128), 256>>>(x, W_in);
    k2_conv<<<dim3((CONVD + NH + 255)/256, Ln/4, Bn), 256>>>(conv_w, conv_b, dt_bias);
    s0_gram<<<Bn*NC, 256>>>();
    s1_intra<<<Bn*NC*NH, 256, S1_SMEM>>>(A_log);
    s2_rec<<<Bn*NH, 512>>>();
    s3_off<<<Bn*NC*NH, 128, S3_SMEM>>>(Dp);
    k4_gate<<<Bn*Ln, 256>>>(rms_w);
    k5_mma<<<dim3(DM/128, (Bn*Ln)/128), 256>>>(W_out);
    k6b_gnfin<<<1, 64>>>();
    k7_mish<<<(Bn*DM*Ln + 255)/256, 256>>>(gn_w, gn_b, out);
}

// round 12
// speedup vs baseline: 1.2022x; 1.0151x over previous
#include <cuda_runtime.h>
#include <math.h>
#include <stdint.h>

#define Bn 8
#define Ln 1024
#define DM 256
#define DI 512
#define NH 16
#define HD 32
#define DS 128
#define CONVD 768
#define DIP 1296
#define Qc 64
#define NC 16   /* Ln/Qc */

// ---------------- scratch (device globals; no mallocs allowed) ----------------
__device__ float g_zx[Bn*Ln*DIP];       // in-proj output
__device__ float g_xs[Bn*Ln*DI];        // conv output, x part (raw, no dt)
__device__ float g_Bmat[Bn*Ln*DS];
__device__ float g_Cmat[Bn*Ln*DS];
__device__ float g_dt[Bn*Ln*NH];
__device__ float g_G[Bn*NC*Qc*Qc];      // TRANSPOSED Gram: Gt[s][t] = C[t]·B[s]
__device__ float g_Acs[Bn*NC*NH*Qc];    // per-chunk inclusive cumsum of dA
__device__ float g_Y[Bn*Ln*DI];         // SSD output accumulator
__device__ float g_st[Bn*NC*NH*HD*DS];  // chunk states -> then prev states
__device__ float g_yf[Bn*Ln*DI];        // gated + rmsnormed
__device__ float g_op[Bn*DM*Ln];        // out-proj, already transposed (b,m,l)
__device__ float g_gnpart[Bn*8*8*2];    // per-(b,g,by) partial sum/sumsq from k5

// ---------------- fast math helpers -----------------------------------------
__device__ __forceinline__ float fsilu(float x){
    return __fdividef(x, 1.f + __expf(-x));
}
__device__ __forceinline__ float fmish(float v){
    float t = 1.f + __expf(v);
    return v - v * __fdividef(2.f, t*t + 1.f);
}

// ---------------- tf32 mma helpers -----------------------------------------
__device__ __forceinline__ uint32_t f2tf32(float f){
    uint32_t r; asm("cvt.rna.tf32.f32 %0, %1;" : "=r"(r) : "f"(f)); return r;
}
__device__ __forceinline__ void mma_tf32(float* c, const uint32_t* a, const uint32_t* b){
    asm volatile("mma.sync.aligned.m16n8k8.row.col.f32.tf32.tf32.f32 "
        "{%0,%1,%2,%3}, {%4,%5,%6,%7}, {%8,%9}, {%0,%1,%2,%3};\n"
        : "+f"(c[0]), "+f"(c[1]), "+f"(c[2]), "+f"(c[3])
        : "r"(a[0]), "r"(a[1]), "r"(a[2]), "r"(a[3]),
          "r"(b[0]), "r"(b[1]));
}

// ---------------- K1: in-proj GEMM via tf32 MMA ----------------------------
// zx[m,n] = sum_c x[b,c,l] * W_in[n,c];  m=(b,l): M=8192, N=1296, K=256
__global__ void __launch_bounds__(256) k1_mma(const float* __restrict__ x,
                                              const float* __restrict__ W){
    __shared__ uint32_t As[2][16][132];   // [k][m]
    __shared__ uint32_t Bs[2][16][132];   // [k][n]
    const int n0 = blockIdx.x * 128;
    const int m0 = blockIdx.y * 128;
    const int b  = m0 >> 10;
    const int l0 = m0 & 1023;
    const int tid = threadIdx.x;
    const int wid = tid >> 5, lane = tid & 31;
    const int wm = wid >> 2, wn = wid & 3;      // warp grid 2(m) x 4(n)
    const int lr = lane >> 2, lc = lane & 3;
    float acc[4][4][4] = {};

    const int a_kk = tid >> 5;
    const int a_mm = (tid & 31) << 2;
    const int b_n  = tid & 127;
    const int b_kq = tid >> 7;
    const int n_glob = n0 + b_n;

    #pragma unroll
    for (int i = 0; i < 2; i++){
        int kk = a_kk + i*8;
        float4 v = *reinterpret_cast<const float4*>(&x[((size_t)b*DM + kk)*Ln + l0 + a_mm]);
        uint32_t* p = &As[0][kk][a_mm];
        p[0]=f2tf32(v.x); p[1]=f2tf32(v.y); p[2]=f2tf32(v.z); p[3]=f2tf32(v.w);
    }
    #pragma unroll
    for (int i = 0; i < 2; i++){
        int kq = b_kq + i*2;
        float4 v = make_float4(0.f,0.f,0.f,0.f);
        if (n_glob < DIP) v = *reinterpret_cast<const float4*>(&W[(size_t)n_glob*DM + kq*4]);
        Bs[0][kq*4+0][b_n]=f2tf32(v.x);
        Bs[0][kq*4+1][b_n]=f2tf32(v.y);
        Bs[0][kq*4+2][b_n]=f2tf32(v.z);
        Bs[0][kq*4+3][b_n]=f2tf32(v.w);
    }
    __syncthreads();

    for (int s = 0; s < 16; s++){
        int buf = s & 1;
        float4 av[2], bv[2];
        if (s < 15){
            int c0 = (s+1)*16;
            #pragma unroll
            for (int i = 0; i < 2; i++){
                int kk = a_kk + i*8;
                av[i] = *reinterpret_cast<const float4*>(&x[((size_t)b*DM + c0 + kk)*Ln + l0 + a_mm]);
            }
            #pragma unroll
            for (int i = 0; i < 2; i++){
                int kq = b_kq + i*2;
                bv[i] = (n_glob < DIP)
                    ? *reinterpret_cast<const float4*>(&W[(size_t)n_glob*DM + c0 + kq*4])
                    : make_float4(0.f,0.f,0.f,0.f);
            }
        }
        #pragma unroll
        for (int ksub = 0; ksub < 2; ksub++){
            int ks = ksub*8;
            uint32_t af[4][4], bf[4][2];
            #pragma unroll
            for (int mi = 0; mi < 4; mi++){
                int mr = wm*64 + mi*16 + lr;
                af[mi][0] = As[buf][ks+lc][mr];
                af[mi][1] = As[buf][ks+lc][mr+8];
                af[mi][2] = As[buf][ks+4+lc][mr];
                af[mi][3] = As[buf][ks+4+lc][mr+8];
            }
            #pragma unroll
            for (int ni = 0; ni < 4; ni++){
                int nc = wn*32 + ni*8 + lr;
                bf[ni][0] = Bs[buf][ks+lc][nc];
                bf[ni][1] = Bs[buf][ks+4+lc][nc];
            }
            #pragma unroll
            for (int mi = 0; mi < 4; mi++)
                #pragma unroll
                for (int ni = 0; ni < 4; ni++)
                    mma_tf32(acc[mi][ni], af[mi], bf[ni]);
        }
        if (s < 15){
            #pragma unroll
            for (int i = 0; i < 2; i++){
                int kk = a_kk + i*8;
                uint32_t* p = &As[buf^1][kk][a_mm];
                p[0]=f2tf32(av[i].x); p[1]=f2tf32(av[i].y); p[2]=f2tf32(av[i].z); p[3]=f2tf32(av[i].w);
            }
            #pragma unroll
            for (int i = 0; i < 2; i++){
                int kq = b_kq + i*2;
                Bs[buf^1][kq*4+0][b_n]=f2tf32(bv[i].x);
                Bs[buf^1][kq*4+1][b_n]=f2tf32(bv[i].y);
                Bs[buf^1][kq*4+2][b_n]=f2tf32(bv[i].z);
                Bs[buf^1][kq*4+3][b_n]=f2tf32(bv[i].w);
            }
            __syncthreads();
        }
    }
    #pragma unroll
    for (int mi = 0; mi < 4; mi++){
        int m = m0 + wm*64 + mi*16 + lr;
        #pragma unroll
        for (int ni = 0; ni < 4; ni++){
            int n = n0 + wn*32 + ni*8 + lc*2;
            if (n < DIP){
                g_zx[(size_t)m*DIP + n]       = acc[mi][ni][0];
                g_zx[(size_t)m*DIP + n + 1]   = acc[mi][ni][1];
                g_zx[(size_t)(m+8)*DIP + n]   = acc[mi][ni][2];
                g_zx[(size_t)(m+8)*DIP + n+1] = acc[mi][ni][3];
            }
        }
    }
}

// ---------------- K2: depthwise conv + SiLU + split, and dt=softplus -------
// 4 channels per thread (float4), 4 l positions per thread.
__global__ void __launch_bounds__(224) k2_conv(const float* __restrict__ conv_w,
                        const float* __restrict__ conv_b,
                        const float* __restrict__ dt_bias){
    int tid = threadIdx.x;
    int l0 = blockIdx.x*4, b = blockIdx.y;
    if (tid < 192){
        int ch = tid*4;
        float4 cw0 = *reinterpret_cast<const float4*>(conv_w + (ch+0)*4);
        float4 cw1 = *reinterpret_cast<const float4*>(conv_w + (ch+1)*4);
        float4 cw2 = *reinterpret_cast<const float4*>(conv_w + (ch+2)*4);
        float4 cw3 = *reinterpret_cast<const float4*>(conv_w + (ch+3)*4);
        float4 bias = *reinterpret_cast<const float4*>(conv_b + ch);
        float4 v[7];
        #pragma unroll
        for (int k = 0; k < 7; k++){
            int ls = l0 - 3 + k;
            v[k] = (ls >= 0)
                ? *reinterpret_cast<const float4*>(&g_zx[((size_t)b*Ln + ls)*DIP + DI + ch])
                : make_float4(0.f,0.f,0.f,0.f);
        }
        #pragma unroll
        for (int j = 0; j < 4; j++){
            float4 r;
            r.x = fsilu(bias.x + cw0.x*v[j].x + cw0.y*v[j+1].x + cw0.z*v[j+2].x + cw0.w*v[j+3].x);
            r.y = fsilu(bias.y + cw1.x*v[j].y + cw1.y*v[j+1].y + cw1.z*v[j+2].y + cw1.w*v[j+3].y);
            r.z = fsilu(bias.z + cw2.x*v[j].z + cw2.y*v[j+1].z + cw2.z*v[j+2].z + cw2.w*v[j+3].z);
            r.w = fsilu(bias.w + cw3.x*v[j].w + cw3.y*v[j+1].w + cw3.z*v[j+2].w + cw3.w*v[j+3].w);
            size_t row = (size_t)b*Ln + l0 + j;
            if (ch < DI)
                *reinterpret_cast<float4*>(&g_xs[row*DI + ch]) = r;
            else if (ch < DI+DS)
                *reinterpret_cast<float4*>(&g_Bmat[row*DS + (ch-DI)]) = r;
            else
                *reinterpret_cast<float4*>(&g_Cmat[row*DS + (ch-DI-DS)]) = r;
        }
    } else if (tid < 192 + NH){
        int hh = tid - 192;
        float db = dt_bias[hh];
        #pragma unroll
        for (int j = 0; j < 4; j++){
            size_t row = (size_t)b*Ln + l0 + j;
            float v = g_zx[row*DIP + DI + CONVD + hh] + db;
            float sp = (v > 20.f) ? v : log1pf(__expf(v));
            g_dt[row*NH + hh] = sp;
        }
    }
}

// ---------------- S0: Gram Gt[b,c,s,t] = C[t]·B[s] (stored transposed) ------
__global__ void s0_gram(){
    __shared__ float Cs[32][65];
    __shared__ float Bs[32][65];
    int bc = blockIdx.x;            // b*NC + c
    int b = bc / NC, c = bc % NC;
    int l0 = c*Qc;
    int tid = threadIdx.x;
    int tx = tid & 15, ty = tid >> 4;
    float acc[4][4] = {};
    for (int n0 = 0; n0 < DS; n0 += 32){
        #pragma unroll
        for (int k = 0; k < 8; k++){
            int idx = tid + k*256;
            int t = idx >> 5, kk = idx & 31;
            Cs[kk][t] = g_Cmat[((size_t)b*Ln + l0 + t)*DS + n0 + kk];
            Bs[kk][t] = g_Bmat[((size_t)b*Ln + l0 + t)*DS + n0 + kk];
        }
        __syncthreads();
        #pragma unroll
        for (int kk = 0; kk < 32; kk++){
            float a[4], bb[4];
            #pragma unroll
            for (int i = 0; i < 4; i++) a[i]  = Bs[kk][ty*4+i];   // rows = s
            #pragma unroll
            for (int j = 0; j < 4; j++) bb[j] = Cs[kk][tx*4+j];   // cols = t
            #pragma unroll
            for (int i = 0; i < 4; i++)
                #pragma unroll
                for (int j = 0; j < 4; j++) acc[i][j] += a[i]*bb[j];
        }
        __syncthreads();
    }
    #pragma unroll
    for (int i = 0; i < 4; i++)
        #pragma unroll
        for (int j = 0; j < 4; j++)
            g_G[((size_t)bc*Qc + ty*4 + i)*Qc + tx*4 + j] = acc[i][j];
}

// ---------------- S1: per (b,chunk,head): scan, Y_diag(MMA), states(MMA) ----
__global__ void __launch_bounds__(256) s1_intra(const float* __restrict__ A_log){
    extern __shared__ float sm[];
    float*    sX   = sm;                         // Qc*36  (X * dt, fp32)
    float*    sB   = sX + Qc*36;                 // Qc*132 (B tile, fp32)
    uint32_t* sWT  = (uint32_t*)(sB + Qc*132);   // Qc*68  (W^T, tf32)
    float*    sAcs = (float*)(sWT + Qc*68);
    float*    sdt  = sAcs + Qc;
    float*    sSe  = sdt + Qc;
    float*    swsum= sSe + Qc;
    int id = blockIdx.x;            // ((b*NC + c)*NH + h)
    int h = id % NH;
    int c = (id / NH) % NC;
    int b = id / (NH*NC);
    int l0 = c*Qc;
    int tid = threadIdx.x;
    int wid = tid >> 5, lane = tid & 31;
    int lr = lane >> 2, lc = lane & 3;

    // warp-shuffle inclusive scan of dA over 64 elements (2 warps)
    float v = 0.f;
    if (tid < Qc){
        float d = g_dt[((size_t)b*Ln + l0 + tid)*NH + h];
        sdt[tid] = d;
        v = d * (-__expf(A_log[h]));
        #pragma unroll
        for (int off = 1; off < 32; off <<= 1){
            float u = __shfl_up_sync(0xffffffffu, v, off);
            if (lane >= off) v += u;
        }
        if (lane == 31) swsum[tid >> 5] = v;
    }
    __syncthreads();
    if (tid < Qc){
        if (tid >= 32) v += swsum[0];
        sAcs[tid] = v;
        g_Acs[(size_t)id*Qc + tid] = v;
    }
    // load X tile scaled by dt
    #pragma unroll
    for (int k = 0; k < 8; k++){
        int idx = tid + k*256;
        int t = idx >> 5, p = idx & 31;
        sX[t*36 + p] = g_xs[(((size_t)b*Ln + l0 + t)*NH + h)*HD + p] * sdt[t];
    }
    // stage B tile (fp32) [t][n], pad 132
    #pragma unroll
    for (int k = 0; k < 8; k++){
        int idx = tid + k*256;
        int t = idx >> 5, c4 = (idx & 31)*4;
        float4 bv = *reinterpret_cast<const float4*>(&g_Bmat[((size_t)b*Ln + l0 + t)*DS + c4]);
        *reinterpret_cast<float4*>(&sB[t*132 + c4]) = bv;
    }
    __syncthreads();

    if (tid < Qc) sSe[tid] = __expf(sAcs[Qc-1] - sAcs[tid]);
    // build W^T (tf32), zero-filled upper triangle: sWT[s][t]
    const float* Gt = g_G + ((size_t)(b*NC + c)*Qc)*Qc;
    #pragma unroll
    for (int k = 0; k < 16; k++){
        int idx = tid + k*256;
        int s_ = idx >> 6, t_ = idx & 63;
        float w = 0.f;
        if (s_ <= t_) w = Gt[s_*Qc + t_] * __expf(sAcs[t_] - sAcs[s_]);
        sWT[s_*68 + t_] = f2tf32(w);
    }
    __syncthreads();

    if (wid < 4){
        // Y_diag = W @ X : M=64(t), N=32(p), K=64(s); warp wid: rows [16w,16w+16)
        const int m0w = wid*16;
        float acc[4][4] = {};
        const int kmax = 2*(wid+1);   // triangular
        for (int k = 0; k < kmax; k++){
            int ks = k*8;
            uint32_t a[4];
            a[0] = sWT[(ks+lc)*68   + m0w + lr];
            a[1] = sWT[(ks+lc)*68   + m0w + lr + 8];
            a[2] = sWT[(ks+4+lc)*68 + m0w + lr];
            a[3] = sWT[(ks+4+lc)*68 + m0w + lr + 8];
            #pragma unroll
            for (int ni = 0; ni < 4; ni++){
                uint32_t bf[2];
                bf[0] = f2tf32(sX[(ks+lc)*36   + ni*8 + lr]);
                bf[1] = f2tf32(sX[(ks+4+lc)*36 + ni*8 + lr]);
                mma_tf32(acc[ni], a, bf);
            }
        }
        #pragma unroll
        for (int ni = 0; ni < 4; ni++){
            int t = m0w + lr;
            int p = ni*8 + lc*2;
            size_t gi = (((size_t)b*Ln + l0 + t)*NH + h)*HD + p;
            *reinterpret_cast<float2*>(&g_Y[gi]) = make_float2(acc[ni][0], acc[ni][1]);
            size_t gi2 = gi + (size_t)8*NH*HD;
            *reinterpret_cast<float2*>(&g_Y[gi2]) = make_float2(acc[ni][2], acc[ni][3]);
        }
    } else {
        // states S = (X*Se)^T @ B : M=32(p), N=128(n), K=64(t)
        const int ww = wid - 4;
        const int p0 = (ww & 1)*16, n0 = (ww >> 1)*64;
        float acc[8][4] = {};
        #pragma unroll
        for (int k = 0; k < 8; k++){
            int ks = k*8;
            int t0 = ks + lc, t1 = ks + 4 + lc;
            float se0 = sSe[t0], se1 = sSe[t1];
            uint32_t a[4];
            a[0] = f2tf32(sX[t0*36 + p0 + lr]     * se0);
            a[1] = f2tf32(sX[t0*36 + p0 + lr + 8] * se0);
            a[2] = f2tf32(sX[t1*36 + p0 + lr]     * se1);
            a[3] = f2tf32(sX[t1*36 + p0 + lr + 8] * se1);
            #pragma unroll
            for (int ni = 0; ni < 8; ni++){
                uint32_t bf[2];
                bf[0] = f2tf32(sB[t0*132 + n0 + ni*8 + lr]);
                bf[1] = f2tf32(sB[t1*132 + n0 + ni*8 + lr]);
                mma_tf32(acc[ni], a, bf);
            }
        }
        float* Sp = g_st + (size_t)id*HD*DS;
        #pragma unroll
        for (int ni = 0; ni < 8; ni++){
            int p = p0 + lr;
            int n = n0 + ni*8 + lc*2;
            *reinterpret_cast<float2*>(&Sp[(size_t)p*DS + n])     = make_float2(acc[ni][0], acc[ni][1]);
            *reinterpret_cast<float2*>(&Sp[(size_t)(p+8)*DS + n]) = make_float2(acc[ni][2], acc[ni][3]);
        }
    }
}

// ---------------- S2: sequential inter-chunk recurrence; writes prev -------
__global__ void __launch_bounds__(512) s2_rec(){
    __shared__ float sdec[NC];
    int bh = blockIdx.x;            // b*NH + h
    int b = bh / NH, h = bh % NH;
    if (threadIdx.x < NC){
        int id = (b*NC + threadIdx.x)*NH + h;
        sdec[threadIdx.x] = __expf(g_Acs[(size_t)id*Qc + Qc - 1]);
    }
    __syncthreads();
    const size_t stride = (size_t)NH*HD*DS;
    size_t base = ((size_t)(b*NC)*NH + h)*HD*DS;
    for (int e = threadIdx.x; e < HD*DS; e += 512){
        float st[NC];
        #pragma unroll
        for (int c = 0; c < NC; c++) st[c] = g_st[base + c*stride + e];
        float prev = 0.f;
        #pragma unroll
        for (int c = 0; c < NC; c++){
            g_st[base + c*stride + e] = prev;
            prev = sdec[c]*prev + st[c];
        }
    }
}

// ---------------- S3: Y_off = exp(Acs[t]) * (C @ prev) + D skip (MMA) -------
__global__ void __launch_bounds__(128) s3_off(const float* __restrict__ Dp){
    extern __shared__ float sm[];
    float* sC = sm;                 // Qc*132 (C tile fp32 [t][n])
    float* sP = sC + Qc*132;        // DS*33  (prev transposed [n][p])
    float* sE = sP + DS*33;         // Qc
    int id = blockIdx.x;
    int h = id % NH;
    int c = (id / NH) % NC;
    int b = id / (NH*NC);
    int l0 = c*Qc;
    int tid = threadIdx.x;
    int wid = tid >> 5, lane = tid & 31;
    int lr = lane >> 2, lc = lane & 3;

    if (tid < Qc) sE[tid] = __expf(g_Acs[(size_t)id*Qc + tid]);
    #pragma unroll
    for (int k = 0; k < 16; k++){
        int idx = tid + k*128;
        int t = idx >> 5, c4 = (idx & 31)*4;
        float4 cv = *reinterpret_cast<const float4*>(&g_Cmat[((size_t)b*Ln + l0 + t)*DS + c4]);
        *reinterpret_cast<float4*>(&sC[t*132 + c4]) = cv;
    }
    const float* Sp = g_st + (size_t)id*HD*DS;
    // HD*DS = 4096 elements staged by 128 threads -> exactly 32 iterations.
    #pragma unroll
    for (int k = 0; k < 32; k++){
        int idx = tid + k*128;
        int p = idx >> 7, n = idx & 127;
        sP[n*33 + p] = Sp[idx];
    }
    __syncthreads();

    // Y_off = C @ prev^T : M=64(t), N=32(p), K=128(n)
    const int m0w = wid*16;
    float acc[4][4] = {};
    #pragma unroll
    for (int k = 0; k < 16; k++){
        int ks = k*8;
        uint32_t a[4];
        a[0] = f2tf32(sC[(m0w+lr)*132   + ks + lc]);
        a[1] = f2tf32(sC[(m0w+lr+8)*132 + ks + lc]);
        a[2] = f2tf32(sC[(m0w+lr)*132   + ks + lc + 4]);
        a[3] = f2tf32(sC[(m0w+lr+8)*132 + ks + lc + 4]);
        #pragma unroll
        for (int ni = 0; ni < 4; ni++){
            uint32_t bf[2];
            bf[0] = f2tf32(sP[(ks+lc)*33   + ni*8 + lr]);
            bf[1] = f2tf32(sP[(ks+4+lc)*33 + ni*8 + lr]);
            mma_tf32(acc[ni], a, bf);
        }
    }
    float dp = Dp[h];
    #pragma unroll
    for (int ni = 0; ni < 4; ni++){
        int t = m0w + lr;
        int p = ni*8 + lc*2;
        float e0 = sE[t], e1 = sE[t+8];
        size_t gi  = (((size_t)b*Ln + l0 + t)*NH + h)*HD + p;
        size_t gi2 = gi + (size_t)8*NH*HD;
        float2 y0 = *reinterpret_cast<float2*>(&g_Y[gi]);
        float2 x0 = *reinterpret_cast<const float2*>(&g_xs[gi]);
        y0.x += e0*acc[ni][0] + dp*x0.x;
        y0.y += e0*acc[ni][1] + dp*x0.y;
        *reinterpret_cast<float2*>(&g_Y[gi]) = y0;
        float2 y1 = *reinterpret_cast<float2*>(&g_Y[gi2]);
        float2 x1 = *reinterpret_cast<const float2*>(&g_xs[gi2]);
        y1.x += e1*acc[ni][2] + dp*x1.x;
        y1.y += e1*acc[ni][3] + dp*x1.y;
        *reinterpret_cast<float2*>(&g_Y[gi2]) = y1;
    }
}

// ---------------- K4: gate with SiLU(z) + RMSNorm over 512 (float4) --------
__global__ void __launch_bounds__(128) k4_gate(const float* __restrict__ rms_w){
    __shared__ float red[4];
    __shared__ float s_r;
    int bl = blockIdx.x;
    int tid = threadIdx.x;
    float4 z4 = *reinterpret_cast<const float4*>(&g_zx[(size_t)bl*DIP + tid*4]);
    float4 y4 = *reinterpret_cast<const float4*>(&g_Y[(size_t)bl*DI + tid*4]);
    float4 v4;
    v4.x = y4.x * fsilu(z4.x);
    v4.y = y4.y * fsilu(z4.y);
    v4.z = y4.z * fsilu(z4.z);
    v4.w = y4.w * fsilu(z4.w);
    float ss = v4.x*v4.x + v4.y*v4.y + v4.z*v4.z + v4.w*v4.w;
    #pragma unroll
    for (int o = 16; o; o >>= 1) ss += __shfl_xor_sync(~0u, ss, o);
    if ((tid & 31) == 0) red[tid >> 5] = ss;
    __syncthreads();
    if (tid == 0){
        float t = red[0] + red[1] + red[2] + red[3];
        s_r = rsqrtf(t/512.f + 1e-5f);
    }
    __syncthreads();
    float r = s_r;
    float4 w4 = *reinterpret_cast<const float4*>(&rms_w[tid*4]);
    v4.x *= r*w4.x; v4.y *= r*w4.y; v4.z *= r*w4.z; v4.w *= r*w4.w;
    *reinterpret_cast<float4*>(&g_yf[(size_t)bl*DI + tid*4]) = v4;
}

// ---------------- K5: out-proj GEMM via tf32 MMA, transposed store ---------
// Epilogue also emits GroupNorm partial sums (each warp's tile is in one group).
__global__ void __launch_bounds__(256) k5_mma(const float* __restrict__ Wout){
    __shared__ uint32_t As[2][16][132];
    __shared__ uint32_t Bs[2][16][132];
    __shared__ float s_part[8][2];
    const int n0 = blockIdx.x * 128;
    const int m0 = blockIdx.y * 128;
    const int tid = threadIdx.x;
    const int wid = tid >> 5, lane = tid & 31;
    const int wm = wid >> 2, wn = wid & 3;
    const int lr = lane >> 2, lc = lane & 3;
    float acc[4][4][4] = {};

    const int t_i  = tid & 127;
    const int t_kq = tid >> 7;

    #pragma unroll
    for (int i = 0; i < 2; i++){
        int kq = t_kq + i*2;
        float4 va = *reinterpret_cast<const float4*>(&g_yf[(size_t)(m0 + t_i)*DI + kq*4]);
        As[0][kq*4+0][t_i]=f2tf32(va.x);
        As[0][kq*4+1][t_i]=f2tf32(va.y);
        As[0][kq*4+2][t_i]=f2tf32(va.z);
        As[0][kq*4+3][t_i]=f2tf32(va.w);
        float4 vb = *reinterpret_cast<const float4*>(&Wout[(size_t)(n0 + t_i)*DI + kq*4]);
        Bs[0][kq*4+0][t_i]=f2tf32(vb.x);
        Bs[0][kq*4+1][t_i]=f2tf32(vb.y);
        Bs[0][kq*4+2][t_i]=f2tf32(vb.z);
        Bs[0][kq*4+3][t_i]=f2tf32(vb.w);
    }
    __syncthreads();

    for (int s = 0; s < 32; s++){
        int buf = s & 1;
        float4 av[2], bv[2];
        if (s < 31){
            int c0 = (s+1)*16;
            #pragma unroll
            for (int i = 0; i < 2; i++){
                int kq = t_kq + i*2;
                av[i] = *reinterpret_cast<const float4*>(&g_yf[(size_t)(m0 + t_i)*DI + c0 + kq*4]);
                bv[i] = *reinterpret_cast<const float4*>(&Wout[(size_t)(n0 + t_i)*DI + c0 + kq*4]);
            }
        }
        #pragma unroll
        for (int ksub = 0; ksub < 2; ksub++){
            int ks = ksub*8;
            uint32_t af[4][4], bf[4][2];
            #pragma unroll
            for (int mi = 0; mi < 4; mi++){
                int mr = wm*64 + mi*16 + lr;
                af[mi][0] = As[buf][ks+lc][mr];
                af[mi][1] = As[buf][ks+lc][mr+8];
                af[mi][2] = As[buf][ks+4+lc][mr];
                af[mi][3] = As[buf][ks+4+lc][mr+8];
            }
            #pragma unroll
            for (int ni = 0; ni < 4; ni++){
                int nc = wn*32 + ni*8 + lr;
                bf[ni][0] = Bs[buf][ks+lc][nc];
                bf[ni][1] = Bs[buf][ks+4+lc][nc];
            }
            #pragma unroll
            for (int mi = 0; mi < 4; mi++)
                #pragma unroll
                for (int ni = 0; ni < 4; ni++)
                    mma_tf32(acc[mi][ni], af[mi], bf[ni]);
        }
        if (s < 31){
            #pragma unroll
            for (int i = 0; i < 2; i++){
                int kq = t_kq + i*2;
                As[buf^1][kq*4+0][t_i]=f2tf32(av[i].x);
                As[buf^1][kq*4+1][t_i]=f2tf32(av[i].y);
                As[buf^1][kq*4+2][t_i]=f2tf32(av[i].z);
                As[buf^1][kq*4+3][t_i]=f2tf32(av[i].w);
                Bs[buf^1][kq*4+0][t_i]=f2tf32(bv[i].x);
                Bs[buf^1][kq*4+1][t_i]=f2tf32(bv[i].y);
                Bs[buf^1][kq*4+2][t_i]=f2tf32(bv[i].z);
                Bs[buf^1][kq*4+3][t_i]=f2tf32(bv[i].w);
            }
            __syncthreads();
        }
    }
    // store transposed + accumulate GroupNorm partials
    float psum = 0.f, psq = 0.f;
    #pragma unroll
    for (int mi = 0; mi < 4; mi++){
        int m = m0 + wm*64 + mi*16 + lr;
        int bb = m >> 10, l = m & 1023;
        #pragma unroll
        for (int ni = 0; ni < 4; ni++){
            int n = n0 + wn*32 + ni*8 + lc*2;
            g_op[((size_t)bb*DM + n  )*Ln + l    ] = acc[mi][ni][0];
            g_op[((size_t)bb*DM + n+1)*Ln + l    ] = acc[mi][ni][1];
            g_op[((size_t)bb*DM + n  )*Ln + l + 8] = acc[mi][ni][2];
            g_op[((size_t)bb*DM + n+1)*Ln + l + 8] = acc[mi][ni][3];
            #pragma unroll
            for (int q = 0; q < 4; q++){
                float vv = acc[mi][ni][q];
                psum += vv; psq += vv*vv;
            }
        }
    }
    #pragma unroll
    for (int o = 16; o; o >>= 1){
        psum += __shfl_xor_sync(~0u, psum, o);
        psq  += __shfl_xor_sync(~0u, psq,  o);
    }
    if (lane == 0){ s_part[wid][0] = psum; s_part[wid][1] = psq; }
    __syncthreads();
    if (tid < 4){
        int g = blockIdx.x*4 + tid;          // global group 0..7
        int b = blockIdx.y >> 3, by = blockIdx.y & 7;
        float S  = s_part[tid][0] + s_part[tid+4][0];
        float S2 = s_part[tid][1] + s_part[tid+4][1];
        int slot = ((b*8 + g)*8 + by)*2;
        g_gnpart[slot]   = S;
        g_gnpart[slot+1] = S2;
    }
}

// ---------------- K7: GN finalize + normalize + affine + Mish (float4) -----
// One block per (b,m) row; thread 0 reduces the 8 partials of its group.
__global__ void __launch_bounds__(256) k7_mish(const float* __restrict__ gn_w,
                        const float* __restrict__ gn_b,
                        float* __restrict__ out){
    __shared__ float s_mu, s_rstd;
    int blk = blockIdx.x;            // b*DM + m
    int b = blk >> 8, m = blk & 255;
    int g = m >> 5;
    if (threadIdx.x == 0){
        double S = 0.0, S2 = 0.0;
        int base = ((b*8 + g)*8)*2;
        #pragma unroll
        for (int by = 0; by < 8; by++){
            S  += (double)g_gnpart[base + by*2];
            S2 += (double)g_gnpart[base + by*2 + 1];
        }
        double N = 32.0*Ln;
        double mu  = S / N;
        double var = S2 / N - mu*mu;
        s_mu   = (float)mu;
        s_rstd = rsqrtf((float)var + 1e-5f);
    }
    __syncthreads();
    float mu = s_mu, r = s_rstd;
    float w = gn_w[m], bo = gn_b[m];
    float4 v4 = *reinterpret_cast<const float4*>(&g_op[(size_t)blk*Ln + threadIdx.x*4]);
    v4.x = fmish((v4.x - mu)*r*w + bo);
    v4.y = fmish((v4.y - mu)*r*w + bo);
    v4.z = fmish((v4.z - mu)*r*w + bo);
    v4.w = fmish((v4.w - mu)*r*w + bo);
    *reinterpret_cast<float4*>(&out[(size_t)blk*Ln + threadIdx.x*4]) = v4;
}

// ---------------------------------------------------------------------------
extern "C" void kernel_launch(void* const* d_in, const int* in_sizes, int n_in,
                              void* d_out, int out_size){
    const float* x       = (const float*)d_in[0];
    const float* W_in    = (const float*)d_in[1];
    const float* conv_w  = (const float*)d_in[2];
    const float* conv_b  = (const float*)d_in[3];
    const float* dt_bias = (const float*)d_in[4];
    const float* A_log   = (const float*)d_in[5];
    const float* Dp      = (const float*)d_in[6];
    const float* rms_w   = (const float*)d_in[7];
    const float* W_out   = (const float*)d_in[8];
    const float* gn_w    = (const float*)d_in[9];
    const float* gn_b    = (const float*)d_in[10];
    float* out = (float*)d_out;

    const int S1_SMEM = (Qc*36 + Qc*132 + Qc*68 + Qc*3 + 2) * 4;   // ~61.2 KB
    const int S3_SMEM = (Qc*132 + DS*33 + Qc) * 4;                  // ~50.9 KB
    cudaFuncSetAttribute(s1_intra, cudaFuncAttributeMaxDynamicSharedMemorySize, S1_SMEM);
    cudaFuncSetAttribute(s3_off,   cudaFuncAttributeMaxDynamicSharedMemorySize, S3_SMEM);

    k1_mma<<<dim3((DIP + 127)/128, (Bn*Ln)/128), 256>>>(x, W_in);
    k2_conv<<<dim3(Ln/4, Bn), 224>>>(conv_w, conv_b, dt_bias);
    s0_gram<<<Bn*NC, 256>>>();
    s1_intra<<<Bn*NC*NH, 256, S1_SMEM>>>(A_log);
    s2_rec<<<Bn*NH, 512>>>();
    s3_off<<<Bn*NC*NH, 128, S3_SMEM>>>(Dp);
    k4_gate<<<Bn*Ln, 128>>>(rms_w);
    k5_mma<<<dim3(DM/128, (Bn*Ln)/128), 256>>>(W_out);
    k7_mish<<<Bn*DM, 256>>>(gn_w, gn_b, out);
}

// round 13
// speedup vs baseline: 1.2178x; 1.0130x over previous
#include <cuda_runtime.h>
#include <math.h>
#include <stdint.h>

#define Bn 8
#define Ln 1024
#define DM 256
#define DI 512
#define NH 16
#define HD 32
#define DS 128
#define CONVD 768
#define DIP 1296
#define Qc 64
#define NC 16   /* Ln/Qc */

// ---------------- scratch (device globals; no mallocs allowed) ----------------
__device__ float g_zx[Bn*Ln*DIP];       // in-proj output
__device__ float g_xs[Bn*Ln*DI];        // conv output, x part (raw, no dt)
__device__ float g_Bmat[Bn*Ln*DS];
__device__ float g_Cmat[Bn*Ln*DS];
__device__ float g_dt[Bn*Ln*NH];
__device__ float g_G[Bn*NC*Qc*Qc];      // TRANSPOSED Gram: Gt[s][t] = C[t]·B[s]
__device__ float g_Acs[Bn*NC*NH*Qc];    // per-chunk inclusive cumsum of dA
__device__ float g_Y[Bn*Ln*DI];         // SSD output accumulator
__device__ float g_st[Bn*NC*NH*HD*DS];  // chunk states -> then prev states
__device__ float g_yf[Bn*Ln*DI];        // gated + rmsnormed
__device__ float g_op[Bn*DM*Ln];        // out-proj, already transposed (b,m,l)
__device__ float g_gnpart[Bn*8*8*2];    // per-(b,g,by) partial sum/sumsq from k5

// ---------------- fast math helpers -----------------------------------------
__device__ __forceinline__ float fsilu(float x){
    return __fdividef(x, 1.f + __expf(-x));
}
__device__ __forceinline__ float fmish(float v){
    float t = 1.f + __expf(v);
    return v - v * __fdividef(2.f, t*t + 1.f);
}

// ---------------- tf32 mma helpers -----------------------------------------
__device__ __forceinline__ uint32_t f2tf32(float f){
    uint32_t r; asm("cvt.rna.tf32.f32 %0, %1;" : "=r"(r) : "f"(f)); return r;
}
__device__ __forceinline__ void mma_tf32(float* c, const uint32_t* a, const uint32_t* b){
    asm volatile("mma.sync.aligned.m16n8k8.row.col.f32.tf32.tf32.f32 "
        "{%0,%1,%2,%3}, {%4,%5,%6,%7}, {%8,%9}, {%0,%1,%2,%3};\n"
        : "+f"(c[0]), "+f"(c[1]), "+f"(c[2]), "+f"(c[3])
        : "r"(a[0]), "r"(a[1]), "r"(a[2]), "r"(a[3]),
          "r"(b[0]), "r"(b[1]));
}

// ---------------- K1: in-proj GEMM via tf32 MMA ----------------------------
// zx[m,n] = sum_c x[b,c,l] * W_in[n,c];  m=(b,l): M=8192, N=1296, K=256
__global__ void __launch_bounds__(256) k1_mma(const float* __restrict__ x,
                                              const float* __restrict__ W){
    __shared__ uint32_t As[2][16][132];   // [k][m]
    __shared__ uint32_t Bs[2][16][132];   // [k][n]
    const int n0 = blockIdx.x * 128;
    const int m0 = blockIdx.y * 128;
    const int b  = m0 >> 10;
    const int l0 = m0 & 1023;
    const int tid = threadIdx.x;
    const int wid = tid >> 5, lane = tid & 31;
    const int wm = wid >> 2, wn = wid & 3;      // warp grid 2(m) x 4(n)
    const int lr = lane >> 2, lc = lane & 3;
    float acc[4][4][4] = {};

    const int a_kk = tid >> 5;
    const int a_mm = (tid & 31) << 2;
    const int b_n  = tid & 127;
    const int b_kq = tid >> 7;
    const int n_glob = n0 + b_n;

    #pragma unroll
    for (int i = 0; i < 2; i++){
        int kk = a_kk + i*8;
        float4 v = *reinterpret_cast<const float4*>(&x[((size_t)b*DM + kk)*Ln + l0 + a_mm]);
        uint32_t* p = &As[0][kk][a_mm];
        p[0]=f2tf32(v.x); p[1]=f2tf32(v.y); p[2]=f2tf32(v.z); p[3]=f2tf32(v.w);
    }
    #pragma unroll
    for (int i = 0; i < 2; i++){
        int kq = b_kq + i*2;
        float4 v = make_float4(0.f,0.f,0.f,0.f);
        if (n_glob < DIP) v = *reinterpret_cast<const float4*>(&W[(size_t)n_glob*DM + kq*4]);
        Bs[0][kq*4+0][b_n]=f2tf32(v.x);
        Bs[0][kq*4+1][b_n]=f2tf32(v.y);
        Bs[0][kq*4+2][b_n]=f2tf32(v.z);
        Bs[0][kq*4+3][b_n]=f2tf32(v.w);
    }
    __syncthreads();

    for (int s = 0; s < 16; s++){
        int buf = s & 1;
        float4 av[2], bv[2];
        if (s < 15){
            int c0 = (s+1)*16;
            #pragma unroll
            for (int i = 0; i < 2; i++){
                int kk = a_kk + i*8;
                av[i] = *reinterpret_cast<const float4*>(&x[((size_t)b*DM + c0 + kk)*Ln + l0 + a_mm]);
            }
            #pragma unroll
            for (int i = 0; i < 2; i++){
                int kq = b_kq + i*2;
                bv[i] = (n_glob < DIP)
                    ? *reinterpret_cast<const float4*>(&W[(size_t)n_glob*DM + c0 + kq*4])
                    : make_float4(0.f,0.f,0.f,0.f);
            }
        }
        #pragma unroll
        for (int ksub = 0; ksub < 2; ksub++){
            int ks = ksub*8;
            uint32_t af[4][4], bf[4][2];
            #pragma unroll
            for (int mi = 0; mi < 4; mi++){
                int mr = wm*64 + mi*16 + lr;
                af[mi][0] = As[buf][ks+lc][mr];
                af[mi][1] = As[buf][ks+lc][mr+8];
                af[mi][2] = As[buf][ks+4+lc][mr];
                af[mi][3] = As[buf][ks+4+lc][mr+8];
            }
            #pragma unroll
            for (int ni = 0; ni < 4; ni++){
                int nc = wn*32 + ni*8 + lr;
                bf[ni][0] = Bs[buf][ks+lc][nc];
                bf[ni][1] = Bs[buf][ks+4+lc][nc];
            }
            #pragma unroll
            for (int mi = 0; mi < 4; mi++)
                #pragma unroll
                for (int ni = 0; ni < 4; ni++)
                    mma_tf32(acc[mi][ni], af[mi], bf[ni]);
        }
        if (s < 15){
            #pragma unroll
            for (int i = 0; i < 2; i++){
                int kk = a_kk + i*8;
                uint32_t* p = &As[buf^1][kk][a_mm];
                p[0]=f2tf32(av[i].x); p[1]=f2tf32(av[i].y); p[2]=f2tf32(av[i].z); p[3]=f2tf32(av[i].w);
            }
            #pragma unroll
            for (int i = 0; i < 2; i++){
                int kq = b_kq + i*2;
                Bs[buf^1][kq*4+0][b_n]=f2tf32(bv[i].x);
                Bs[buf^1][kq*4+1][b_n]=f2tf32(bv[i].y);
                Bs[buf^1][kq*4+2][b_n]=f2tf32(bv[i].z);
                Bs[buf^1][kq*4+3][b_n]=f2tf32(bv[i].w);
            }
            __syncthreads();
        }
    }
    #pragma unroll
    for (int mi = 0; mi < 4; mi++){
        int m = m0 + wm*64 + mi*16 + lr;
        #pragma unroll
        for (int ni = 0; ni < 4; ni++){
            int n = n0 + wn*32 + ni*8 + lc*2;
            if (n < DIP){
                g_zx[(size_t)m*DIP + n]       = acc[mi][ni][0];
                g_zx[(size_t)m*DIP + n + 1]   = acc[mi][ni][1];
                g_zx[(size_t)(m+8)*DIP + n]   = acc[mi][ni][2];
                g_zx[(size_t)(m+8)*DIP + n+1] = acc[mi][ni][3];
            }
        }
    }
}

// ---------------- K2: depthwise conv + SiLU + split, and dt=softplus -------
__global__ void __launch_bounds__(224) k2_conv(const float* __restrict__ conv_w,
                        const float* __restrict__ conv_b,
                        const float* __restrict__ dt_bias){
    int tid = threadIdx.x;
    int l0 = blockIdx.x*4, b = blockIdx.y;
    if (tid < 192){
        int ch = tid*4;
        float4 cw0 = *reinterpret_cast<const float4*>(conv_w + (ch+0)*4);
        float4 cw1 = *reinterpret_cast<const float4*>(conv_w + (ch+1)*4);
        float4 cw2 = *reinterpret_cast<const float4*>(conv_w + (ch+2)*4);
        float4 cw3 = *reinterpret_cast<const float4*>(conv_w + (ch+3)*4);
        float4 bias = *reinterpret_cast<const float4*>(conv_b + ch);
        float4 v[7];
        #pragma unroll
        for (int k = 0; k < 7; k++){
            int ls = l0 - 3 + k;
            v[k] = (ls >= 0)
                ? *reinterpret_cast<const float4*>(&g_zx[((size_t)b*Ln + ls)*DIP + DI + ch])
                : make_float4(0.f,0.f,0.f,0.f);
        }
        #pragma unroll
        for (int j = 0; j < 4; j++){
            float4 r;
            r.x = fsilu(bias.x + cw0.x*v[j].x + cw0.y*v[j+1].x + cw0.z*v[j+2].x + cw0.w*v[j+3].x);
            r.y = fsilu(bias.y + cw1.x*v[j].y + cw1.y*v[j+1].y + cw1.z*v[j+2].y + cw1.w*v[j+3].y);
            r.z = fsilu(bias.z + cw2.x*v[j].z + cw2.y*v[j+1].z + cw2.z*v[j+2].z + cw2.w*v[j+3].z);
            r.w = fsilu(bias.w + cw3.x*v[j].w + cw3.y*v[j+1].w + cw3.z*v[j+2].w + cw3.w*v[j+3].w);
            size_t row = (size_t)b*Ln + l0 + j;
            if (ch < DI)
                *reinterpret_cast<float4*>(&g_xs[row*DI + ch]) = r;
            else if (ch < DI+DS)
                *reinterpret_cast<float4*>(&g_Bmat[row*DS + (ch-DI)]) = r;
            else
                *reinterpret_cast<float4*>(&g_Cmat[row*DS + (ch-DI-DS)]) = r;
        }
    } else if (tid < 192 + NH){
        int hh = tid - 192;
        float db = dt_bias[hh];
        #pragma unroll
        for (int j = 0; j < 4; j++){
            size_t row = (size_t)b*Ln + l0 + j;
            float v = g_zx[row*DIP + DI + CONVD + hh] + db;
            float sp = (v > 20.f) ? v : log1pf(__expf(v));
            g_dt[row*NH + hh] = sp;
        }
    }
}

// ---------------- S0: Gram Gt[b,c,s,t] = C[t]·B[s] (stored transposed) ------
__global__ void s0_gram(){
    __shared__ float Cs[32][65];
    __shared__ float Bs[32][65];
    int bc = blockIdx.x;            // b*NC + c
    int b = bc / NC, c = bc % NC;
    int l0 = c*Qc;
    int tid = threadIdx.x;
    int tx = tid & 15, ty = tid >> 4;
    float acc[4][4] = {};
    for (int n0 = 0; n0 < DS; n0 += 32){
        #pragma unroll
        for (int k = 0; k < 8; k++){
            int idx = tid + k*256;
            int t = idx >> 5, kk = idx & 31;
            Cs[kk][t] = g_Cmat[((size_t)b*Ln + l0 + t)*DS + n0 + kk];
            Bs[kk][t] = g_Bmat[((size_t)b*Ln + l0 + t)*DS + n0 + kk];
        }
        __syncthreads();
        #pragma unroll
        for (int kk = 0; kk < 32; kk++){
            float a[4], bb[4];
            #pragma unroll
            for (int i = 0; i < 4; i++) a[i]  = Bs[kk][ty*4+i];   // rows = s
            #pragma unroll
            for (int j = 0; j < 4; j++) bb[j] = Cs[kk][tx*4+j];   // cols = t
            #pragma unroll
            for (int i = 0; i < 4; i++)
                #pragma unroll
                for (int j = 0; j < 4; j++) acc[i][j] += a[i]*bb[j];
        }
        __syncthreads();
    }
    #pragma unroll
    for (int i = 0; i < 4; i++)
        #pragma unroll
        for (int j = 0; j < 4; j++)
            g_G[((size_t)bc*Qc + ty*4 + i)*Qc + tx*4 + j] = acc[i][j];
}

// ---------------- S1: per (b,chunk,head): scan, Y_diag(MMA), states(MMA) ----
// All MMA operands pre-converted to tf32 at staging; inner loops pure LDS+MMA.
// Se folded into the staged B tile (S = sum_t (X*dt)[t,p] * (B*Se)[t,n]).
__global__ void __launch_bounds__(256) s1_intra(const float* __restrict__ A_log){
    extern __shared__ float sm[];
    uint32_t* sXT  = (uint32_t*)sm;              // Qc*36  tf32(X*dt)
    uint32_t* sBT  = sXT + Qc*36;                // Qc*132 tf32(B*Se)
    uint32_t* sWT  = sBT + Qc*132;               // Qc*68  tf32(W^T)
    float*    sAcs = (float*)(sWT + Qc*68);
    float*    sdt  = sAcs + Qc;
    float*    sSe  = sdt + Qc;
    float*    swsum= sSe + Qc;
    int id = blockIdx.x;            // ((b*NC + c)*NH + h)
    int h = id % NH;
    int c = (id / NH) % NC;
    int b = id / (NH*NC);
    int l0 = c*Qc;
    int tid = threadIdx.x;
    int wid = tid >> 5, lane = tid & 31;
    int lr = lane >> 2, lc = lane & 3;

    // warp-shuffle inclusive scan of dA over 64 elements (2 warps)
    float v = 0.f;
    if (tid < Qc){
        float d = g_dt[((size_t)b*Ln + l0 + tid)*NH + h];
        sdt[tid] = d;
        v = d * (-__expf(A_log[h]));
        #pragma unroll
        for (int off = 1; off < 32; off <<= 1){
            float u = __shfl_up_sync(0xffffffffu, v, off);
            if (lane >= off) v += u;
        }
        if (lane == 31) swsum[tid >> 5] = v;
    }
    __syncthreads();
    float tot = swsum[0] + swsum[1];   // Acs[Qc-1]
    if (tid < Qc){
        if (tid >= 32) v += swsum[0];
        sAcs[tid] = v;
        g_Acs[(size_t)id*Qc + tid] = v;
        sSe[tid] = __expf(tot - v);
    }
    // stage X*dt as tf32
    #pragma unroll
    for (int k = 0; k < 8; k++){
        int idx = tid + k*256;
        int t = idx >> 5, p = idx & 31;
        sXT[t*36 + p] = f2tf32(g_xs[(((size_t)b*Ln + l0 + t)*NH + h)*HD + p] * sdt[t]);
    }
    __syncthreads();

    // stage B*Se as tf32 [t][n] (pad 132), and build W^T (tf32)
    #pragma unroll
    for (int k = 0; k < 8; k++){
        int idx = tid + k*256;
        int t = idx >> 5, c4 = (idx & 31)*4;
        float4 bv = *reinterpret_cast<const float4*>(&g_Bmat[((size_t)b*Ln + l0 + t)*DS + c4]);
        float se = sSe[t];
        uint4 u;
        u.x = f2tf32(bv.x*se); u.y = f2tf32(bv.y*se);
        u.z = f2tf32(bv.z*se); u.w = f2tf32(bv.w*se);
        *reinterpret_cast<uint4*>(&sBT[t*132 + c4]) = u;
    }
    const float* Gt = g_G + ((size_t)(b*NC + c)*Qc)*Qc;
    #pragma unroll
    for (int k = 0; k < 16; k++){
        int idx = tid + k*256;
        int s_ = idx >> 6, t_ = idx & 63;
        float w = 0.f;
        if (s_ <= t_) w = Gt[s_*Qc + t_] * __expf(sAcs[t_] - sAcs[s_]);
        sWT[s_*68 + t_] = f2tf32(w);
    }
    __syncthreads();

    if (wid < 4){
        // Y_diag = W @ (X*dt) : M=64(t), N=32(p), K=64(s)
        const int m0w = wid*16;
        float acc[4][4] = {};
        const int kmax = 2*(wid+1);   // triangular
        for (int k = 0; k < kmax; k++){
            int ks = k*8;
            uint32_t a[4];
            a[0] = sWT[(ks+lc)*68   + m0w + lr];
            a[1] = sWT[(ks+lc)*68   + m0w + lr + 8];
            a[2] = sWT[(ks+4+lc)*68 + m0w + lr];
            a[3] = sWT[(ks+4+lc)*68 + m0w + lr + 8];
            #pragma unroll
            for (int ni = 0; ni < 4; ni++){
                uint32_t bf[2];
                bf[0] = sXT[(ks+lc)*36   + ni*8 + lr];
                bf[1] = sXT[(ks+4+lc)*36 + ni*8 + lr];
                mma_tf32(acc[ni], a, bf);
            }
        }
        #pragma unroll
        for (int ni = 0; ni < 4; ni++){
            int t = m0w + lr;
            int p = ni*8 + lc*2;
            size_t gi = (((size_t)b*Ln + l0 + t)*NH + h)*HD + p;
            *reinterpret_cast<float2*>(&g_Y[gi]) = make_float2(acc[ni][0], acc[ni][1]);
            size_t gi2 = gi + (size_t)8*NH*HD;
            *reinterpret_cast<float2*>(&g_Y[gi2]) = make_float2(acc[ni][2], acc[ni][3]);
        }
    } else {
        // states S = (X*dt)^T @ (B*Se) : M=32(p), N=128(n), K=64(t)
        const int ww = wid - 4;
        const int p0 = (ww & 1)*16, n0 = (ww >> 1)*64;
        float acc[8][4] = {};
        #pragma unroll
        for (int k = 0; k < 8; k++){
            int ks = k*8;
            int t0 = ks + lc, t1 = ks + 4 + lc;
            uint32_t a[4];
            a[0] = sXT[t0*36 + p0 + lr];
            a[1] = sXT[t0*36 + p0 + lr + 8];
            a[2] = sXT[t1*36 + p0 + lr];
            a[3] = sXT[t1*36 + p0 + lr + 8];
            #pragma unroll
            for (int ni = 0; ni < 8; ni++){
                uint32_t bf[2];
                bf[0] = sBT[t0*132 + n0 + ni*8 + lr];
                bf[1] = sBT[t1*132 + n0 + ni*8 + lr];
                mma_tf32(acc[ni], a, bf);
            }
        }
        float* Sp = g_st + (size_t)id*HD*DS;
        #pragma unroll
        for (int ni = 0; ni < 8; ni++){
            int p = p0 + lr;
            int n = n0 + ni*8 + lc*2;
            *reinterpret_cast<float2*>(&Sp[(size_t)p*DS + n])     = make_float2(acc[ni][0], acc[ni][1]);
            *reinterpret_cast<float2*>(&Sp[(size_t)(p+8)*DS + n]) = make_float2(acc[ni][2], acc[ni][3]);
        }
    }
}

// ---------------- S2: sequential inter-chunk recurrence; writes prev -------
__global__ void __launch_bounds__(512) s2_rec(){
    __shared__ float sdec[NC];
    int bh = blockIdx.x;            // b*NH + h
    int b = bh / NH, h = bh % NH;
    if (threadIdx.x < NC){
        int id = (b*NC + threadIdx.x)*NH + h;
        sdec[threadIdx.x] = __expf(g_Acs[(size_t)id*Qc + Qc - 1]);
    }
    __syncthreads();
    const size_t stride = (size_t)NH*HD*DS;
    size_t base = ((size_t)(b*NC)*NH + h)*HD*DS;
    for (int e = threadIdx.x; e < HD*DS; e += 512){
        float st[NC];
        #pragma unroll
        for (int c = 0; c < NC; c++) st[c] = g_st[base + c*stride + e];
        float prev = 0.f;
        #pragma unroll
        for (int c = 0; c < NC; c++){
            g_st[base + c*stride + e] = prev;
            prev = sdec[c]*prev + st[c];
        }
    }
}

// ---------------- S3: Y_off = exp(Acs[t]) * (C @ prev) + D skip (MMA) -------
// Operands pre-converted to tf32 at staging; inner loop pure LDS+MMA.
__global__ void __launch_bounds__(128) s3_off(const float* __restrict__ Dp){
    extern __shared__ float sm[];
    uint32_t* sCT = (uint32_t*)sm;   // Qc*132 tf32(C) [t][n]
    uint32_t* sPT = sCT + Qc*132;    // DS*33  tf32(prev^T) [n][p]
    float*    sE  = (float*)(sPT + DS*33);   // Qc
    int id = blockIdx.x;
    int h = id % NH;
    int c = (id / NH) % NC;
    int b = id / (NH*NC);
    int l0 = c*Qc;
    int tid = threadIdx.x;
    int wid = tid >> 5, lane = tid & 31;
    int lr = lane >> 2, lc = lane & 3;

    if (tid < Qc) sE[tid] = __expf(g_Acs[(size_t)id*Qc + tid]);
    #pragma unroll
    for (int k = 0; k < 16; k++){
        int idx = tid + k*128;
        int t = idx >> 5, c4 = (idx & 31)*4;
        float4 cv = *reinterpret_cast<const float4*>(&g_Cmat[((size_t)b*Ln + l0 + t)*DS + c4]);
        uint4 u;
        u.x = f2tf32(cv.x); u.y = f2tf32(cv.y); u.z = f2tf32(cv.z); u.w = f2tf32(cv.w);
        *reinterpret_cast<uint4*>(&sCT[t*132 + c4]) = u;
    }
    const float* Sp = g_st + (size_t)id*HD*DS;
    // HD*DS = 4096 elements staged by 128 threads -> exactly 32 iterations.
    #pragma unroll
    for (int k = 0; k < 32; k++){
        int idx = tid + k*128;
        int p = idx >> 7, n = idx & 127;
        sPT[n*33 + p] = f2tf32(Sp[idx]);
    }
    __syncthreads();

    // Y_off = C @ prev^T : M=64(t), N=32(p), K=128(n)
    const int m0w = wid*16;
    float acc[4][4] = {};
    #pragma unroll
    for (int k = 0; k < 16; k++){
        int ks = k*8;
        uint32_t a[4];
        a[0] = sCT[(m0w+lr)*132   + ks + lc];
        a[1] = sCT[(m0w+lr+8)*132 + ks + lc];
        a[2] = sCT[(m0w+lr)*132   + ks + lc + 4];
        a[3] = sCT[(m0w+lr+8)*132 + ks + lc + 4];
        #pragma unroll
        for (int ni = 0; ni < 4; ni++){
            uint32_t bf[2];
            bf[0] = sPT[(ks+lc)*33   + ni*8 + lr];
            bf[1] = sPT[(ks+4+lc)*33 + ni*8 + lr];
            mma_tf32(acc[ni], a, bf);
        }
    }
    float dp = Dp[h];
    #pragma unroll
    for (int ni = 0; ni < 4; ni++){
        int t = m0w + lr;
        int p = ni*8 + lc*2;
        float e0 = sE[t], e1 = sE[t+8];
        size_t gi  = (((size_t)b*Ln + l0 + t)*NH + h)*HD + p;
        size_t gi2 = gi + (size_t)8*NH*HD;
        float2 y0 = *reinterpret_cast<float2*>(&g_Y[gi]);
        float2 x0 = *reinterpret_cast<const float2*>(&g_xs[gi]);
        y0.x += e0*acc[ni][0] + dp*x0.x;
        y0.y += e0*acc[ni][1] + dp*x0.y;
        *reinterpret_cast<float2*>(&g_Y[gi]) = y0;
        float2 y1 = *reinterpret_cast<float2*>(&g_Y[gi2]);
        float2 x1 = *reinterpret_cast<const float2*>(&g_xs[gi2]);
        y1.x += e1*acc[ni][2] + dp*x1.x;
        y1.y += e1*acc[ni][3] + dp*x1.y;
        *reinterpret_cast<float2*>(&g_Y[gi2]) = y1;
    }
}

// ---------------- K4: gate with SiLU(z) + RMSNorm over 512 (float4) --------
__global__ void __launch_bounds__(128) k4_gate(const float* __restrict__ rms_w){
    __shared__ float red[4];
    __shared__ float s_r;
    int bl = blockIdx.x;
    int tid = threadIdx.x;
    float4 z4 = *reinterpret_cast<const float4*>(&g_zx[(size_t)bl*DIP + tid*4]);
    float4 y4 = *reinterpret_cast<const float4*>(&g_Y[(size_t)bl*DI + tid*4]);
    float4 v4;
    v4.x = y4.x * fsilu(z4.x);
    v4.y = y4.y * fsilu(z4.y);
    v4.z = y4.z * fsilu(z4.z);
    v4.w = y4.w * fsilu(z4.w);
    float ss = v4.x*v4.x + v4.y*v4.y + v4.z*v4.z + v4.w*v4.w;
    #pragma unroll
    for (int o = 16; o; o >>= 1) ss += __shfl_xor_sync(~0u, ss, o);
    if ((tid & 31) == 0) red[tid >> 5] = ss;
    __syncthreads();
    if (tid == 0){
        float t = red[0] + red[1] + red[2] + red[3];
        s_r = rsqrtf(t/512.f + 1e-5f);
    }
    __syncthreads();
    float r = s_r;
    float4 w4 = *reinterpret_cast<const float4*>(&rms_w[tid*4]);
    v4.x *= r*w4.x; v4.y *= r*w4.y; v4.z *= r*w4.z; v4.w *= r*w4.w;
    *reinterpret_cast<float4*>(&g_yf[(size_t)bl*DI + tid*4]) = v4;
}

// ---------------- K5: out-proj GEMM via tf32 MMA, transposed store ---------
// Epilogue also emits GroupNorm partial sums (each warp's tile is in one group).
__global__ void __launch_bounds__(256) k5_mma(const float* __restrict__ Wout){
    __shared__ uint32_t As[2][16][132];
    __shared__ uint32_t Bs[2][16][132];
    __shared__ float s_part[8][2];
    const int n0 = blockIdx.x * 128;
    const int m0 = blockIdx.y * 128;
    const int tid = threadIdx.x;
    const int wid = tid >> 5, lane = tid & 31;
    const int wm = wid >> 2, wn = wid & 3;
    const int lr = lane >> 2, lc = lane & 3;
    float acc[4][4][4] = {};

    const int t_i  = tid & 127;
    const int t_kq = tid >> 7;

    #pragma unroll
    for (int i = 0; i < 2; i++){
        int kq = t_kq + i*2;
        float4 va = *reinterpret_cast<const float4*>(&g_yf[(size_t)(m0 + t_i)*DI + kq*4]);
        As[0][kq*4+0][t_i]=f2tf32(va.x);
        As[0][kq*4+1][t_i]=f2tf32(va.y);
        As[0][kq*4+2][t_i]=f2tf32(va.z);
        As[0][kq*4+3][t_i]=f2tf32(va.w);
        float4 vb = *reinterpret_cast<const float4*>(&Wout[(size_t)(n0 + t_i)*DI + kq*4]);
        Bs[0][kq*4+0][t_i]=f2tf32(vb.x);
        Bs[0][kq*4+1][t_i]=f2tf32(vb.y);
        Bs[0][kq*4+2][t_i]=f2tf32(vb.z);
        Bs[0][kq*4+3][t_i]=f2tf32(vb.w);
    }
    __syncthreads();

    for (int s = 0; s < 32; s++){
        int buf = s & 1;
        float4 av[2], bv[2];
        if (s < 31){
            int c0 = (s+1)*16;
            #pragma unroll
            for (int i = 0; i < 2; i++){
                int kq = t_kq + i*2;
                av[i] = *reinterpret_cast<const float4*>(&g_yf[(size_t)(m0 + t_i)*DI + c0 + kq*4]);
                bv[i] = *reinterpret_cast<const float4*>(&Wout[(size_t)(n0 + t_i)*DI + c0 + kq*4]);
            }
        }
        #pragma unroll
        for (int ksub = 0; ksub < 2; ksub++){
            int ks = ksub*8;
            uint32_t af[4][4], bf[4][2];
            #pragma unroll
            for (int mi = 0; mi < 4; mi++){
                int mr = wm*64 + mi*16 + lr;
                af[mi][0] = As[buf][ks+lc][mr];
                af[mi][1] = As[buf][ks+lc][mr+8];
                af[mi][2] = As[buf][ks+4+lc][mr];
                af[mi][3] = As[buf][ks+4+lc][mr+8];
            }
            #pragma unroll
            for (int ni = 0; ni < 4; ni++){
                int nc = wn*32 + ni*8 + lr;
                bf[ni][0] = Bs[buf][ks+lc][nc];
                bf[ni][1] = Bs[buf][ks+4+lc][nc];
            }
            #pragma unroll
            for (int mi = 0; mi < 4; mi++)
                #pragma unroll
                for (int ni = 0; ni < 4; ni++)
                    mma_tf32(acc[mi][ni], af[mi], bf[ni]);
        }
        if (s < 31){
            #pragma unroll
            for (int i = 0; i < 2; i++){
                int kq = t_kq + i*2;
                As[buf^1][kq*4+0][t_i]=f2tf32(av[i].x);
                As[buf^1][kq*4+1][t_i]=f2tf32(av[i].y);
                As[buf^1][kq*4+2][t_i]=f2tf32(av[i].z);
                As[buf^1][kq*4+3][t_i]=f2tf32(av[i].w);
                Bs[buf^1][kq*4+0][t_i]=f2tf32(bv[i].x);
                Bs[buf^1][kq*4+1][t_i]=f2tf32(bv[i].y);
                Bs[buf^1][kq*4+2][t_i]=f2tf32(bv[i].z);
                Bs[buf^1][kq*4+3][t_i]=f2tf32(bv[i].w);
            }
            __syncthreads();
        }
    }
    // store transposed + accumulate GroupNorm partials
    float psum = 0.f, psq = 0.f;
    #pragma unroll
    for (int mi = 0; mi < 4; mi++){
        int m = m0 + wm*64 + mi*16 + lr;
        int bb = m >> 10, l = m & 1023;
        #pragma unroll
        for (int ni = 0; ni < 4; ni++){
            int n = n0 + wn*32 + ni*8 + lc*2;
            g_op[((size_t)bb*DM + n  )*Ln + l    ] = acc[mi][ni][0];
            g_op[((size_t)bb*DM + n+1)*Ln + l    ] = acc[mi][ni][1];
            g_op[((size_t)bb*DM + n  )*Ln + l + 8] = acc[mi][ni][2];
            g_op[((size_t)bb*DM + n+1)*Ln + l + 8] = acc[mi][ni][3];
            #pragma unroll
            for (int q = 0; q < 4; q++){
                float vv = acc[mi][ni][q];
                psum += vv; psq += vv*vv;
            }
        }
    }
    #pragma unroll
    for (int o = 16; o; o >>= 1){
        psum += __shfl_xor_sync(~0u, psum, o);
        psq  += __shfl_xor_sync(~0u, psq,  o);
    }
    if (lane == 0){ s_part[wid][0] = psum; s_part[wid][1] = psq; }
    __syncthreads();
    if (tid < 4){
        int g = blockIdx.x*4 + tid;          // global group 0..7
        int b = blockIdx.y >> 3, by = blockIdx.y & 7;
        float S  = s_part[tid][0] + s_part[tid+4][0];
        float S2 = s_part[tid][1] + s_part[tid+4][1];
        int slot = ((b*8 + g)*8 + by)*2;
        g_gnpart[slot]   = S;
        g_gnpart[slot+1] = S2;
    }
}

// ---------------- K7: GN finalize + normalize + affine + Mish (float4) -----
__global__ void __launch_bounds__(256) k7_mish(const float* __restrict__ gn_w,
                        const float* __restrict__ gn_b,
                        float* __restrict__ out){
    __shared__ float s_mu, s_rstd;
    int blk = blockIdx.x;            // b*DM + m
    int b = blk >> 8, m = blk & 255;
    int g = m >> 5;
    if (threadIdx.x == 0){
        double S = 0.0, S2 = 0.0;
        int base = ((b*8 + g)*8)*2;
        #pragma unroll
        for (int by = 0; by < 8; by++){
            S  += (double)g_gnpart[base + by*2];
            S2 += (double)g_gnpart[base + by*2 + 1];
        }
        double N = 32.0*Ln;
        double mu  = S / N;
        double var = S2 / N - mu*mu;
        s_mu   = (float)mu;
        s_rstd = rsqrtf((float)var + 1e-5f);
    }
    __syncthreads();
    float mu = s_mu, r = s_rstd;
    float w = gn_w[m], bo = gn_b[m];
    float4 v4 = *reinterpret_cast<const float4*>(&g_op[(size_t)blk*Ln + threadIdx.x*4]);
    v4.x = fmish((v4.x - mu)*r*w + bo);
    v4.y = fmish((v4.y - mu)*r*w + bo);
    v4.z = fmish((v4.z - mu)*r*w + bo);
    v4.w = fmish((v4.w - mu)*r*w + bo);
    *reinterpret_cast<float4*>(&out[(size_t)blk*Ln + threadIdx.x*4]) = v4;
}

// ---------------------------------------------------------------------------
extern "C" void kernel_launch(void* const* d_in, const int* in_sizes, int n_in,
                              void* d_out, int out_size){
    const float* x       = (const float*)d_in[0];
    const float* W_in    = (const float*)d_in[1];
    const float* conv_w  = (const float*)d_in[2];
    const float* conv_b  = (const float*)d_in[3];
    const float* dt_bias = (const float*)d_in[4];
    const float* A_log   = (const float*)d_in[5];
    const float* Dp      = (const float*)d_in[6];
    const float* rms_w   = (const float*)d_in[7];
    const float* W_out   = (const float*)d_in[8];
    const float* gn_w    = (const float*)d_in[9];
    const float* gn_b    = (const float*)d_in[10];
    float* out = (float*)d_out;

    const int S1_SMEM = (Qc*36 + Qc*132 + Qc*68 + Qc*3 + 2) * 4;   // ~61.2 KB
    const int S3_SMEM = (Qc*132 + DS*33 + Qc) * 4;                  // ~50.9 KB
    cudaFuncSetAttribute(s1_intra, cudaFuncAttributeMaxDynamicSharedMemorySize, S1_SMEM);
    cudaFuncSetAttribute(s3_off,   cudaFuncAttributeMaxDynamicSharedMemorySize, S3_SMEM);

    k1_mma<<<dim3((DIP + 127)/128, (Bn*Ln)/128), 256>>>(x, W_in);
    k2_conv<<<dim3(Ln/4, Bn), 224>>>(conv_w, conv_b, dt_bias);
    s0_gram<<<Bn*NC, 256>>>();
    s1_intra<<<Bn*NC*NH, 256, S1_SMEM>>>(A_log);
    s2_rec<<<Bn*NH, 512>>>();
    s3_off<<<Bn*NC*NH, 128, S3_SMEM>>>(Dp);
    k4_gate<<<Bn*Ln, 128>>>(rms_w);
    k5_mma<<<dim3(DM/128, (Bn*Ln)/128), 256>>>(W_out);
    k7_mish<<<Bn*DM, 256>>>(gn_w, gn_b, out);
}